// round 2
// baseline (speedup 1.0000x reference)
#include <cuda_runtime.h>
#include <math.h>

#define NB 8
#define NH 8
#define NP_ 1025
#define NPAD 1024
#define DH 64
#define EM 512
#define MROWS (NB * NP_)   // 8200

// Scratch (static device globals -- no runtime allocation)
__device__ float g_q[NB * NH * NP_ * DH];
__device__ float g_k[NB * NH * NP_ * DH];
__device__ float g_v[NB * NH * NP_ * DH];
__device__ float g_ctx[NB * NP_ * EM];
__device__ unsigned char g_mask[NB * NPAD * NPAD];
__device__ int g_mask_mode;

// ---------------------------------------------------------------------------
// Mask dtype detection: classify the raw buffer as float32 / int32 / uint8.
// Random 0/1 data makes misclassification vanishingly unlikely.
// ---------------------------------------------------------------------------
__global__ void mask_detect_kernel(const unsigned int* __restrict__ pm)
{
    if (blockIdx.x == 0 && threadIdx.x == 0) {
        bool allFloat = true, allInt = true;
        for (int i = 0; i < 4096; i++) {
            unsigned int w = pm[i];
            if (!(w == 0u || w == 0x3F800000u)) allFloat = false;
            if (w > 1u) allInt = false;
        }
        g_mask_mode = allFloat ? 0 : (allInt ? 1 : 2);
    }
}

__global__ __launch_bounds__(256) void mask_convert_kernel(const void* __restrict__ pm)
{
    const int mode = g_mask_mode;
    const size_t n = (size_t)NB * NPAD * NPAD;
    const size_t stride = (size_t)gridDim.x * blockDim.x;
    for (size_t i = (size_t)blockIdx.x * blockDim.x + threadIdx.x; i < n; i += stride) {
        unsigned char v;
        if (mode == 0)      v = (((const float*)pm)[i] != 0.f) ? 1 : 0;
        else if (mode == 1) v = (((const int*)pm)[i] != 0) ? 1 : 0;
        else                v = (((const unsigned char*)pm)[i] != 0) ? 1 : 0;
        g_mask[i] = v;
    }
}

// ---------------------------------------------------------------------------
// GEMM: C[m, j] = sum_k A[m,k] * W[j,k] + bias[j]   (i.e. A @ W^T + b)
// MODE 0/1/2: A = x, out = g_q/g_k/g_v in [B,H,NP,D] head layout
// MODE 3:     A = g_ctx, out = outp plain [MROWS, 512]
// Tiles: 64x64x16, 256 threads, 4x4 per thread.
// ---------------------------------------------------------------------------
template <int MODE>
__global__ __launch_bounds__(256) void gemm_kernel(
    const float* __restrict__ A_in,
    const float* __restrict__ W,
    const float* __restrict__ bias,
    float* __restrict__ outp)
{
    __shared__ float As[16][68];
    __shared__ float Bs[16][68];

    const float* A = (MODE == 3) ? g_ctx : A_in;
    float* out;
    if (MODE == 0) out = g_q;
    else if (MODE == 1) out = g_k;
    else if (MODE == 2) out = g_v;
    else out = outp;

    const int m0 = blockIdx.x * 64;
    const int n0 = blockIdx.y * 64;
    const int t  = threadIdx.x;
    const int tx = t & 15;
    const int ty = t >> 4;
    const int lr = t >> 2;          // 0..63 : tile row for loads
    const int lc = (t & 3) << 2;    // 0,4,8,12 : k-chunk for loads

    float acc[4][4];
#pragma unroll
    for (int i = 0; i < 4; i++)
#pragma unroll
        for (int j = 0; j < 4; j++) acc[i][j] = 0.f;

    for (int k0 = 0; k0 < EM; k0 += 16) {
        // load A tile (64 x 16), transposed into As[k][m]
        {
            const int gm = m0 + lr;
            float4 av = make_float4(0.f, 0.f, 0.f, 0.f);
            if (gm < MROWS)
                av = *(const float4*)(A + (size_t)gm * EM + k0 + lc);
            As[lc + 0][lr] = av.x;
            As[lc + 1][lr] = av.y;
            As[lc + 2][lr] = av.z;
            As[lc + 3][lr] = av.w;
        }
        // load W tile (64 x 16) -> Bs[k][n]
        {
            float4 bv = *(const float4*)(W + (size_t)(n0 + lr) * EM + k0 + lc);
            Bs[lc + 0][lr] = bv.x;
            Bs[lc + 1][lr] = bv.y;
            Bs[lc + 2][lr] = bv.z;
            Bs[lc + 3][lr] = bv.w;
        }
        __syncthreads();
#pragma unroll
        for (int kk = 0; kk < 16; kk++) {
            float4 a4 = *(float4*)&As[kk][ty << 2];
            float4 b4 = *(float4*)&Bs[kk][tx << 2];
            acc[0][0] += a4.x * b4.x; acc[0][1] += a4.x * b4.y;
            acc[0][2] += a4.x * b4.z; acc[0][3] += a4.x * b4.w;
            acc[1][0] += a4.y * b4.x; acc[1][1] += a4.y * b4.y;
            acc[1][2] += a4.y * b4.z; acc[1][3] += a4.y * b4.w;
            acc[2][0] += a4.z * b4.x; acc[2][1] += a4.z * b4.y;
            acc[2][2] += a4.z * b4.z; acc[2][3] += a4.z * b4.w;
            acc[3][0] += a4.w * b4.x; acc[3][1] += a4.w * b4.y;
            acc[3][2] += a4.w * b4.z; acc[3][3] += a4.w * b4.w;
        }
        __syncthreads();
    }

    const float4 bb = *(const float4*)(bias + n0 + (tx << 2));
#pragma unroll
    for (int i = 0; i < 4; i++) {
        const int row = m0 + (ty << 2) + i;
        if (row >= MROWS) continue;
        float4 r4 = make_float4(acc[i][0] + bb.x, acc[i][1] + bb.y,
                                acc[i][2] + bb.z, acc[i][3] + bb.w);
        if (MODE < 3) {
            const int b = row / NP_;
            const int n = row - b * NP_;
            const int h = blockIdx.y;   // TILE_N == DH == 64
            const size_t idx = ((size_t)(b * NH + h) * NP_ + n) * DH + (tx << 2);
            *(float4*)(out + idx) = r4;
        } else {
            *(float4*)(out + (size_t)row * EM + n0 + (tx << 2)) = r4;
        }
    }
}

// ---------------------------------------------------------------------------
// Flash-attention style kernel with fused bias + padding mask.
// Block: 32 queries x (one b,h). Key tiles of 64. 256 threads.
// S phase: thread = 2 rows x 4 keys. AV phase: thread = 1 row x 8 dims.
// smem: qs 8K + ks 16K (XOR swizzled) + vs 16K + ps 8K = 48K exactly.
// ---------------------------------------------------------------------------
__global__ __launch_bounds__(256) void attn_kernel(
    const float* __restrict__ abias)
{
    __shared__ float qs[32][DH];
    __shared__ float ks[64][DH];   // swizzled
    __shared__ float vs[64][DH];
    __shared__ float ps[32][64];   // swizzled

    const int bh = blockIdx.y;
    const int b  = bh >> 3;
    const int h  = bh & 7;
    const int q0 = blockIdx.x * 32;
    const int t  = threadIdx.x;

    const float* qptr = g_q + (size_t)bh * NP_ * DH;
    const float* kptr = g_k + (size_t)bh * NP_ * DH;
    const float* vptr = g_v + (size_t)bh * NP_ * DH;

    // --- load Q tile ---
    {
        const int row = t >> 3;
        const int d0  = (t & 7) * 8;
        const int gq  = q0 + row;
        if (gq < NP_) {
            const float* src = qptr + (size_t)gq * DH + d0;
            *(float4*)&qs[row][d0]     = *(const float4*)src;
            *(float4*)&qs[row][d0 + 4] = *(const float4*)(src + 4);
        } else {
            float4 z = make_float4(0.f, 0.f, 0.f, 0.f);
            *(float4*)&qs[row][d0] = z;
            *(float4*)&qs[row][d0 + 4] = z;
        }
    }

    // --- S mapping: 2 rows x 4 keys ---
    const int kg   = t & 15;
    const int rp   = t >> 4;
    const int kk0  = kg * 4;
    const int row0 = rp * 2;
    const int sw   = ((kk0 >> 3) & 7) << 3;         // k-tile swizzle (const per thread)
    const int psw0 = (row0 & 3) << 4;               // ps swizzle, row0
    const int psw1 = ((row0 + 1) & 3) << 4;         // ps swizzle, row0+1

    // --- AV mapping: 1 row x 8 dims ---
    const int r    = t >> 3;
    const int c8   = t & 7;
    const int d0o  = c8 * 8;
    const int psr  = (r & 3) << 4;
    const int lane = t & 31;
    const int lr4  = lane >> 3;                     // 0..3 local row in warp
    const int srcl = (lr4 >> 1) << 4;               // shfl source lane (0 or 16)
    const int sel1 = lr4 & 1;                       // pick c1 vs c0

    const int gq0 = q0 + row0;
    const int gq1 = q0 + row0 + 1;
    const bool v0 = gq0 < NP_;
    const bool v1 = gq1 < NP_;
    const float* brow0 = abias + ((size_t)bh * NP_ + (v0 ? gq0 : 0)) * NP_;
    const float* brow1 = abias + ((size_t)bh * NP_ + (v1 ? gq1 : 0)) * NP_;
    const unsigned char* mrow0 = g_mask + ((size_t)b * NPAD + (gq0 > 0 ? gq0 - 1 : 0)) * NPAD;
    const unsigned char* mrow1 = g_mask + ((size_t)b * NPAD + (gq1 > 0 ? gq1 - 1 : 0)) * NPAD;

    float m0v = -INFINITY, m1v = -INFINITY;
    float l0 = 0.f, l1 = 0.f;
    float o[8];
#pragma unroll
    for (int j = 0; j < 8; j++) o[j] = 0.f;

    const int nkt = (NP_ + 63) / 64;  // 17
    for (int kt = 0; kt < nkt; kt++) {
        const int kbase = kt * 64;
        __syncthreads();
        // --- load K (swizzled) and V tiles ---
        {
            const int row = t >> 2;
            const int dd  = (t & 3) * 16;
            const int gk  = kbase + row;
            const int swl = ((row >> 3) & 7) << 3;
            if (gk < NP_) {
                const float* kg_ = kptr + (size_t)gk * DH + dd;
                const float* vg_ = vptr + (size_t)gk * DH + dd;
#pragma unroll
                for (int i = 0; i < 16; i += 4) {
                    *(float4*)&ks[row][(dd + i) ^ swl] = *(const float4*)(kg_ + i);
                    *(float4*)&vs[row][dd + i]         = *(const float4*)(vg_ + i);
                }
            } else {
                float4 z = make_float4(0.f, 0.f, 0.f, 0.f);
#pragma unroll
                for (int i = 0; i < 16; i += 4) {
                    *(float4*)&ks[row][(dd + i) ^ swl] = z;
                    *(float4*)&vs[row][dd + i]         = z;
                }
            }
        }
        __syncthreads();

        // --- S = Q K^T ---
        float s0[4] = {0.f, 0.f, 0.f, 0.f};
        float s1[4] = {0.f, 0.f, 0.f, 0.f};
#pragma unroll
        for (int d = 0; d < DH; d += 4) {
            float4 qa = *(float4*)&qs[row0][d];
            float4 qb = *(float4*)&qs[row0 + 1][d];
#pragma unroll
            for (int j = 0; j < 4; j++) {
                float4 k4 = *(float4*)&ks[kk0 + j][d ^ sw];
                s0[j] += qa.x * k4.x + qa.y * k4.y + qa.z * k4.z + qa.w * k4.w;
                s1[j] += qb.x * k4.x + qb.y * k4.y + qb.z * k4.z + qb.w * k4.w;
            }
        }

        // --- fused scale + bias + padding mask ---
        if (v0) {
#pragma unroll
            for (int j = 0; j < 4; j++) {
                const int gk = kbase + kk0 + j;
                if (gk < NP_) {
                    float add = 0.f;
                    if (gq0 > 0 && gk > 0)
                        add = mrow0[gk - 1] ? 0.f : -INFINITY;
                    s0[j] = s0[j] * 0.125f + __ldg(brow0 + gk) + add;
                } else s0[j] = -INFINITY;
            }
        } else {
#pragma unroll
            for (int j = 0; j < 4; j++) s0[j] = 0.f;
        }
        if (v1) {
#pragma unroll
            for (int j = 0; j < 4; j++) {
                const int gk = kbase + kk0 + j;
                if (gk < NP_) {
                    float add = 0.f;
                    if (gq1 > 0 && gk > 0)
                        add = mrow1[gk - 1] ? 0.f : -INFINITY;
                    s1[j] = s1[j] * 0.125f + __ldg(brow1 + gk) + add;
                } else s1[j] = -INFINITY;
            }
        } else {
#pragma unroll
            for (int j = 0; j < 4; j++) s1[j] = 0.f;
        }

        // --- online softmax (row reduce over 16 lanes) ---
        float t0 = fmaxf(fmaxf(s0[0], s0[1]), fmaxf(s0[2], s0[3]));
        float t1 = fmaxf(fmaxf(s1[0], s1[1]), fmaxf(s1[2], s1[3]));
#pragma unroll
        for (int off = 8; off; off >>= 1) {
            t0 = fmaxf(t0, __shfl_xor_sync(0xffffffffu, t0, off));
            t1 = fmaxf(t1, __shfl_xor_sync(0xffffffffu, t1, off));
        }
        const float mn0 = fmaxf(m0v, t0);
        const float mn1 = fmaxf(m1v, t1);
        const float c0 = __expf(m0v - mn0);
        const float c1 = __expf(m1v - mn1);
        float p0s = 0.f, p1s = 0.f;
#pragma unroll
        for (int j = 0; j < 4; j++) {
            float p0 = __expf(s0[j] - mn0);
            float p1 = __expf(s1[j] - mn1);
            ps[row0][(kk0 + j) ^ psw0]     = p0;
            ps[row0 + 1][(kk0 + j) ^ psw1] = p1;
            p0s += p0;
            p1s += p1;
        }
#pragma unroll
        for (int off = 8; off; off >>= 1) {
            p0s += __shfl_xor_sync(0xffffffffu, p0s, off);
            p1s += __shfl_xor_sync(0xffffffffu, p1s, off);
        }
        l0 = l0 * c0 + p0s;
        l1 = l1 * c1 + p1s;
        m0v = mn0;
        m1v = mn1;

        // broadcast correction factor for AV-mapping row via intra-warp shfl
        const float cA = __shfl_sync(0xffffffffu, c0, srcl);
        const float cB = __shfl_sync(0xffffffffu, c1, srcl);
        const float cr = sel1 ? cB : cA;

        __syncthreads();

        // --- O = O*corr + P V ---
#pragma unroll
        for (int j = 0; j < 8; j++) o[j] *= cr;
#pragma unroll
        for (int kk = 0; kk < 64; kk++) {
            const float pf = ps[r][kk ^ psr];
            float4 va = *(float4*)&vs[kk][d0o];
            float4 vb = *(float4*)&vs[kk][d0o + 4];
            o[0] += pf * va.x; o[1] += pf * va.y;
            o[2] += pf * va.z; o[3] += pf * va.w;
            o[4] += pf * vb.x; o[5] += pf * vb.y;
            o[6] += pf * vb.z; o[7] += pf * vb.w;
        }
    }

    // --- finalize: 1/l broadcast, write ctx in [B,NP,E] layout ---
    const float i0 = (l0 > 0.f) ? 1.f / l0 : 0.f;
    const float i1 = (l1 > 0.f) ? 1.f / l1 : 0.f;
    const float iA = __shfl_sync(0xffffffffu, i0, srcl);
    const float iB = __shfl_sync(0xffffffffu, i1, srcl);
    const float inv = sel1 ? iB : iA;

    const int gqr = q0 + r;
    if (gqr < NP_) {
        float* dst = g_ctx + ((size_t)b * NP_ + gqr) * EM + h * DH + d0o;
        float4 ra = make_float4(o[0] * inv, o[1] * inv, o[2] * inv, o[3] * inv);
        float4 rb = make_float4(o[4] * inv, o[5] * inv, o[6] * inv, o[7] * inv);
        *(float4*)dst       = ra;
        *(float4*)(dst + 4) = rb;
    }
}

// ---------------------------------------------------------------------------
extern "C" void kernel_launch(void* const* d_in, const int* in_sizes, int n_in,
                              void* d_out, int out_size)
{
    const float* x     = (const float*)d_in[0];
    const float* abias = (const float*)d_in[1];
    const void*  pmask = (const void*)d_in[2];
    const float* Wq = (const float*)d_in[3];
    const float* bq = (const float*)d_in[4];
    const float* Wk = (const float*)d_in[5];
    const float* bk = (const float*)d_in[6];
    const float* Wv = (const float*)d_in[7];
    const float* bv = (const float*)d_in[8];
    const float* Wo = (const float*)d_in[9];
    const float* bo = (const float*)d_in[10];
    float* out = (float*)d_out;

    // --- normalize pad_mask to uint8 regardless of delivered dtype ---
    mask_detect_kernel<<<1, 32>>>((const unsigned int*)pmask);
    mask_convert_kernel<<<1024, 256>>>(pmask);

    dim3 gg((MROWS + 63) / 64, EM / 64, 1);   // 129 x 8

    gemm_kernel<0><<<gg, 256>>>(x, Wq, bq, nullptr);
    gemm_kernel<1><<<gg, 256>>>(x, Wk, bk, nullptr);
    gemm_kernel<2><<<gg, 256>>>(x, Wv, bv, nullptr);

    dim3 ga((NP_ + 31) / 32, NB * NH, 1);     // 33 x 64
    attn_kernel<<<ga, 256>>>(abias);

    gemm_kernel<3><<<gg, 256>>>(nullptr, Wo, bo, out);
}

// round 3
// speedup vs baseline: 1.0016x; 1.0016x over previous
#include <cuda_runtime.h>
#include <math.h>

#define NB 8
#define NH 8
#define NP_ 1025
#define NPAD 1024
#define DH 64
#define EM 512
#define MROWS (NB * NP_)   // 8200

// Scratch (static device globals -- no runtime allocation)
__device__ float g_q[NB * NH * NP_ * DH];
__device__ float g_k[NB * NH * NP_ * DH];
__device__ float g_v[NB * NH * NP_ * DH];
__device__ float g_ctx[NB * NP_ * EM];
__device__ unsigned char g_mask[NB * NPAD * NPAD];
__device__ int g_mask_mode;

// ---------------------------------------------------------------------------
// Mask dtype detection: classify the raw buffer as float32 / int32 / uint8.
// Random 0/1 data makes misclassification vanishingly unlikely.
// ---------------------------------------------------------------------------
__global__ void mask_detect_kernel(const unsigned int* __restrict__ pm)
{
    if (blockIdx.x == 0 && threadIdx.x == 0) {
        bool allFloat = true, allInt = true;
        for (int i = 0; i < 4096; i++) {
            unsigned int w = pm[i];
            if (!(w == 0u || w == 0x3F800000u)) allFloat = false;
            if (w > 1u) allInt = false;
        }
        g_mask_mode = allFloat ? 0 : (allInt ? 1 : 2);
    }
}

__global__ __launch_bounds__(256) void mask_convert_kernel(const void* __restrict__ pm)
{
    const int mode = g_mask_mode;
    const size_t n = (size_t)NB * NPAD * NPAD;
    const size_t stride = (size_t)gridDim.x * blockDim.x;
    for (size_t i = (size_t)blockIdx.x * blockDim.x + threadIdx.x; i < n; i += stride) {
        unsigned char v;
        if (mode == 0)      v = (((const float*)pm)[i] != 0.f) ? 1 : 0;
        else if (mode == 1) v = (((const int*)pm)[i] != 0) ? 1 : 0;
        else                v = (((const unsigned char*)pm)[i] != 0) ? 1 : 0;
        g_mask[i] = v;
    }
}

// ---------------------------------------------------------------------------
// GEMM: C[m, j] = sum_k A[m,k] * W[j,k] + bias[j]   (i.e. A @ W^T + b)
// MODE 0/1/2: A = x, out = g_q/g_k/g_v in [B,H,NP,D] head layout
// MODE 3:     A = g_ctx, out = outp plain [MROWS, 512]
// Tiles: 64x64x16, 256 threads, 4x4 per thread.
// ---------------------------------------------------------------------------
template <int MODE>
__global__ __launch_bounds__(256) void gemm_kernel(
    const float* __restrict__ A_in,
    const float* __restrict__ W,
    const float* __restrict__ bias,
    float* __restrict__ outp)
{
    __shared__ float As[16][68];
    __shared__ float Bs[16][68];

    const float* A = (MODE == 3) ? g_ctx : A_in;
    float* out;
    if (MODE == 0) out = g_q;
    else if (MODE == 1) out = g_k;
    else if (MODE == 2) out = g_v;
    else out = outp;

    const int m0 = blockIdx.x * 64;
    const int n0 = blockIdx.y * 64;
    const int t  = threadIdx.x;
    const int tx = t & 15;
    const int ty = t >> 4;
    const int lr = t >> 2;          // 0..63 : tile row for loads
    const int lc = (t & 3) << 2;    // 0,4,8,12 : k-chunk for loads

    float acc[4][4];
#pragma unroll
    for (int i = 0; i < 4; i++)
#pragma unroll
        for (int j = 0; j < 4; j++) acc[i][j] = 0.f;

    for (int k0 = 0; k0 < EM; k0 += 16) {
        // load A tile (64 x 16), transposed into As[k][m]
        {
            const int gm = m0 + lr;
            float4 av = make_float4(0.f, 0.f, 0.f, 0.f);
            if (gm < MROWS)
                av = *(const float4*)(A + (size_t)gm * EM + k0 + lc);
            As[lc + 0][lr] = av.x;
            As[lc + 1][lr] = av.y;
            As[lc + 2][lr] = av.z;
            As[lc + 3][lr] = av.w;
        }
        // load W tile (64 x 16) -> Bs[k][n]
        {
            float4 bv = *(const float4*)(W + (size_t)(n0 + lr) * EM + k0 + lc);
            Bs[lc + 0][lr] = bv.x;
            Bs[lc + 1][lr] = bv.y;
            Bs[lc + 2][lr] = bv.z;
            Bs[lc + 3][lr] = bv.w;
        }
        __syncthreads();
#pragma unroll
        for (int kk = 0; kk < 16; kk++) {
            float4 a4 = *(float4*)&As[kk][ty << 2];
            float4 b4 = *(float4*)&Bs[kk][tx << 2];
            acc[0][0] += a4.x * b4.x; acc[0][1] += a4.x * b4.y;
            acc[0][2] += a4.x * b4.z; acc[0][3] += a4.x * b4.w;
            acc[1][0] += a4.y * b4.x; acc[1][1] += a4.y * b4.y;
            acc[1][2] += a4.y * b4.z; acc[1][3] += a4.y * b4.w;
            acc[2][0] += a4.z * b4.x; acc[2][1] += a4.z * b4.y;
            acc[2][2] += a4.z * b4.z; acc[2][3] += a4.z * b4.w;
            acc[3][0] += a4.w * b4.x; acc[3][1] += a4.w * b4.y;
            acc[3][2] += a4.w * b4.z; acc[3][3] += a4.w * b4.w;
        }
        __syncthreads();
    }

    const float4 bb = *(const float4*)(bias + n0 + (tx << 2));
#pragma unroll
    for (int i = 0; i < 4; i++) {
        const int row = m0 + (ty << 2) + i;
        if (row >= MROWS) continue;
        float4 r4 = make_float4(acc[i][0] + bb.x, acc[i][1] + bb.y,
                                acc[i][2] + bb.z, acc[i][3] + bb.w);
        if (MODE < 3) {
            const int b = row / NP_;
            const int n = row - b * NP_;
            const int h = blockIdx.y;   // TILE_N == DH == 64
            const size_t idx = ((size_t)(b * NH + h) * NP_ + n) * DH + (tx << 2);
            *(float4*)(out + idx) = r4;
        } else {
            *(float4*)(out + (size_t)row * EM + n0 + (tx << 2)) = r4;
        }
    }
}

// ---------------------------------------------------------------------------
// Flash-attention style kernel with fused bias + padding mask.
// Block: 32 queries x (one b,h). Key tiles of 64. 256 threads.
// S phase: thread = 2 rows x 4 keys. AV phase: thread = 1 row x 8 dims.
// smem: qs 8K + ks 16K (XOR swizzled) + vs 16K + ps 8K = 48K exactly.
// ---------------------------------------------------------------------------
__global__ __launch_bounds__(256) void attn_kernel(
    const float* __restrict__ abias)
{
    __shared__ float qs[32][DH];
    __shared__ float ks[64][DH];   // swizzled
    __shared__ float vs[64][DH];
    __shared__ float ps[32][64];   // swizzled

    const int bh = blockIdx.y;
    const int b  = bh >> 3;
    const int h  = bh & 7;
    const int q0 = blockIdx.x * 32;
    const int t  = threadIdx.x;

    const float* qptr = g_q + (size_t)bh * NP_ * DH;
    const float* kptr = g_k + (size_t)bh * NP_ * DH;
    const float* vptr = g_v + (size_t)bh * NP_ * DH;

    // --- load Q tile ---
    {
        const int row = t >> 3;
        const int d0  = (t & 7) * 8;
        const int gq  = q0 + row;
        if (gq < NP_) {
            const float* src = qptr + (size_t)gq * DH + d0;
            *(float4*)&qs[row][d0]     = *(const float4*)src;
            *(float4*)&qs[row][d0 + 4] = *(const float4*)(src + 4);
        } else {
            float4 z = make_float4(0.f, 0.f, 0.f, 0.f);
            *(float4*)&qs[row][d0] = z;
            *(float4*)&qs[row][d0 + 4] = z;
        }
    }

    // --- S mapping: 2 rows x 4 keys ---
    const int kg   = t & 15;
    const int rp   = t >> 4;
    const int kk0  = kg * 4;
    const int row0 = rp * 2;
    const int sw   = ((kk0 >> 3) & 7) << 3;         // k-tile swizzle (const per thread)
    const int psw0 = (row0 & 3) << 4;               // ps swizzle, row0
    const int psw1 = ((row0 + 1) & 3) << 4;         // ps swizzle, row0+1

    // --- AV mapping: 1 row x 8 dims ---
    const int r    = t >> 3;
    const int c8   = t & 7;
    const int d0o  = c8 * 8;
    const int psr  = (r & 3) << 4;
    const int lane = t & 31;
    const int lr4  = lane >> 3;                     // 0..3 local row in warp
    const int srcl = (lr4 >> 1) << 4;               // shfl source lane (0 or 16)
    const int sel1 = lr4 & 1;                       // pick c1 vs c0

    const int gq0 = q0 + row0;
    const int gq1 = q0 + row0 + 1;
    const bool v0 = gq0 < NP_;
    const bool v1 = gq1 < NP_;
    const float* brow0 = abias + ((size_t)bh * NP_ + (v0 ? gq0 : 0)) * NP_;
    const float* brow1 = abias + ((size_t)bh * NP_ + (v1 ? gq1 : 0)) * NP_;
    const unsigned char* mrow0 = g_mask + ((size_t)b * NPAD + (gq0 > 0 ? gq0 - 1 : 0)) * NPAD;
    const unsigned char* mrow1 = g_mask + ((size_t)b * NPAD + (gq1 > 0 ? gq1 - 1 : 0)) * NPAD;

    float m0v = -INFINITY, m1v = -INFINITY;
    float l0 = 0.f, l1 = 0.f;
    float o[8];
#pragma unroll
    for (int j = 0; j < 8; j++) o[j] = 0.f;

    const int nkt = (NP_ + 63) / 64;  // 17
    for (int kt = 0; kt < nkt; kt++) {
        const int kbase = kt * 64;
        __syncthreads();
        // --- load K (swizzled) and V tiles ---
        {
            const int row = t >> 2;
            const int dd  = (t & 3) * 16;
            const int gk  = kbase + row;
            const int swl = ((row >> 3) & 7) << 3;
            if (gk < NP_) {
                const float* kg_ = kptr + (size_t)gk * DH + dd;
                const float* vg_ = vptr + (size_t)gk * DH + dd;
#pragma unroll
                for (int i = 0; i < 16; i += 4) {
                    *(float4*)&ks[row][(dd + i) ^ swl] = *(const float4*)(kg_ + i);
                    *(float4*)&vs[row][dd + i]         = *(const float4*)(vg_ + i);
                }
            } else {
                float4 z = make_float4(0.f, 0.f, 0.f, 0.f);
#pragma unroll
                for (int i = 0; i < 16; i += 4) {
                    *(float4*)&ks[row][(dd + i) ^ swl] = z;
                    *(float4*)&vs[row][dd + i]         = z;
                }
            }
        }
        __syncthreads();

        // --- S = Q K^T ---
        float s0[4] = {0.f, 0.f, 0.f, 0.f};
        float s1[4] = {0.f, 0.f, 0.f, 0.f};
#pragma unroll
        for (int d = 0; d < DH; d += 4) {
            float4 qa = *(float4*)&qs[row0][d];
            float4 qb = *(float4*)&qs[row0 + 1][d];
#pragma unroll
            for (int j = 0; j < 4; j++) {
                float4 k4 = *(float4*)&ks[kk0 + j][d ^ sw];
                s0[j] += qa.x * k4.x + qa.y * k4.y + qa.z * k4.z + qa.w * k4.w;
                s1[j] += qb.x * k4.x + qb.y * k4.y + qb.z * k4.z + qb.w * k4.w;
            }
        }

        // --- fused scale + bias + padding mask ---
        if (v0) {
#pragma unroll
            for (int j = 0; j < 4; j++) {
                const int gk = kbase + kk0 + j;
                if (gk < NP_) {
                    float add = 0.f;
                    if (gq0 > 0 && gk > 0)
                        add = mrow0[gk - 1] ? 0.f : -INFINITY;
                    s0[j] = s0[j] * 0.125f + __ldg(brow0 + gk) + add;
                } else s0[j] = -INFINITY;
            }
        } else {
#pragma unroll
            for (int j = 0; j < 4; j++) s0[j] = 0.f;
        }
        if (v1) {
#pragma unroll
            for (int j = 0; j < 4; j++) {
                const int gk = kbase + kk0 + j;
                if (gk < NP_) {
                    float add = 0.f;
                    if (gq1 > 0 && gk > 0)
                        add = mrow1[gk - 1] ? 0.f : -INFINITY;
                    s1[j] = s1[j] * 0.125f + __ldg(brow1 + gk) + add;
                } else s1[j] = -INFINITY;
            }
        } else {
#pragma unroll
            for (int j = 0; j < 4; j++) s1[j] = 0.f;
        }

        // --- online softmax (row reduce over 16 lanes) ---
        float t0 = fmaxf(fmaxf(s0[0], s0[1]), fmaxf(s0[2], s0[3]));
        float t1 = fmaxf(fmaxf(s1[0], s1[1]), fmaxf(s1[2], s1[3]));
#pragma unroll
        for (int off = 8; off; off >>= 1) {
            t0 = fmaxf(t0, __shfl_xor_sync(0xffffffffu, t0, off));
            t1 = fmaxf(t1, __shfl_xor_sync(0xffffffffu, t1, off));
        }
        const float mn0 = fmaxf(m0v, t0);
        const float mn1 = fmaxf(m1v, t1);
        const float c0 = __expf(m0v - mn0);
        const float c1 = __expf(m1v - mn1);
        float p0s = 0.f, p1s = 0.f;
#pragma unroll
        for (int j = 0; j < 4; j++) {
            float p0 = __expf(s0[j] - mn0);
            float p1 = __expf(s1[j] - mn1);
            ps[row0][(kk0 + j) ^ psw0]     = p0;
            ps[row0 + 1][(kk0 + j) ^ psw1] = p1;
            p0s += p0;
            p1s += p1;
        }
#pragma unroll
        for (int off = 8; off; off >>= 1) {
            p0s += __shfl_xor_sync(0xffffffffu, p0s, off);
            p1s += __shfl_xor_sync(0xffffffffu, p1s, off);
        }
        l0 = l0 * c0 + p0s;
        l1 = l1 * c1 + p1s;
        m0v = mn0;
        m1v = mn1;

        // broadcast correction factor for AV-mapping row via intra-warp shfl
        const float cA = __shfl_sync(0xffffffffu, c0, srcl);
        const float cB = __shfl_sync(0xffffffffu, c1, srcl);
        const float cr = sel1 ? cB : cA;

        __syncthreads();

        // --- O = O*corr + P V ---
#pragma unroll
        for (int j = 0; j < 8; j++) o[j] *= cr;
#pragma unroll
        for (int kk = 0; kk < 64; kk++) {
            const float pf = ps[r][kk ^ psr];
            float4 va = *(float4*)&vs[kk][d0o];
            float4 vb = *(float4*)&vs[kk][d0o + 4];
            o[0] += pf * va.x; o[1] += pf * va.y;
            o[2] += pf * va.z; o[3] += pf * va.w;
            o[4] += pf * vb.x; o[5] += pf * vb.y;
            o[6] += pf * vb.z; o[7] += pf * vb.w;
        }
    }

    // --- finalize: 1/l broadcast, write ctx in [B,NP,E] layout ---
    const float i0 = (l0 > 0.f) ? 1.f / l0 : 0.f;
    const float i1 = (l1 > 0.f) ? 1.f / l1 : 0.f;
    const float iA = __shfl_sync(0xffffffffu, i0, srcl);
    const float iB = __shfl_sync(0xffffffffu, i1, srcl);
    const float inv = sel1 ? iB : iA;

    const int gqr = q0 + r;
    if (gqr < NP_) {
        float* dst = g_ctx + ((size_t)b * NP_ + gqr) * EM + h * DH + d0o;
        float4 ra = make_float4(o[0] * inv, o[1] * inv, o[2] * inv, o[3] * inv);
        float4 rb = make_float4(o[4] * inv, o[5] * inv, o[6] * inv, o[7] * inv);
        *(float4*)dst       = ra;
        *(float4*)(dst + 4) = rb;
    }
}

// ---------------------------------------------------------------------------
extern "C" void kernel_launch(void* const* d_in, const int* in_sizes, int n_in,
                              void* d_out, int out_size)
{
    const float* x     = (const float*)d_in[0];
    const float* abias = (const float*)d_in[1];
    const void*  pmask = (const void*)d_in[2];
    const float* Wq = (const float*)d_in[3];
    const float* bq = (const float*)d_in[4];
    const float* Wk = (const float*)d_in[5];
    const float* bk = (const float*)d_in[6];
    const float* Wv = (const float*)d_in[7];
    const float* bv = (const float*)d_in[8];
    const float* Wo = (const float*)d_in[9];
    const float* bo = (const float*)d_in[10];
    float* out = (float*)d_out;

    // --- normalize pad_mask to uint8 regardless of delivered dtype ---
    mask_detect_kernel<<<1, 32>>>((const unsigned int*)pmask);
    mask_convert_kernel<<<1024, 256>>>(pmask);

    dim3 gg((MROWS + 63) / 64, EM / 64, 1);   // 129 x 8

    gemm_kernel<0><<<gg, 256>>>(x, Wq, bq, nullptr);
    gemm_kernel<1><<<gg, 256>>>(x, Wk, bk, nullptr);
    gemm_kernel<2><<<gg, 256>>>(x, Wv, bv, nullptr);

    dim3 ga((NP_ + 31) / 32, NB * NH, 1);     // 33 x 64
    attn_kernel<<<ga, 256>>>(abias);

    gemm_kernel<3><<<gg, 256>>>(nullptr, Wo, bo, out);
}

// round 9
// speedup vs baseline: 3.3138x; 3.3085x over previous
#include <cuda_runtime.h>
#include <cuda_bf16.h>
#include <math.h>
#include <stdint.h>

#define NB 8
#define NH 8
#define NP_ 1025
#define NPAD 1024
#define DH 64
#define EM 512
#define MROWS (NB * NP_)      // 8200
#define XE (MROWS * EM)       // 4198400
#define WE (EM * EM)          // 262144

__device__ __align__(16) __nv_bfloat16 g_xh[XE], g_xl[XE];
__device__ __align__(16) __nv_bfloat16 g_wh[4][WE], g_wl[4][WE];
__device__ __align__(16) __nv_bfloat16 g_qh[XE], g_ql[XE];
__device__ __align__(16) __nv_bfloat16 g_kh[XE], g_kl[XE];
__device__ __align__(16) __nv_bfloat16 g_vh[XE], g_vl[XE];
__device__ __align__(16) __nv_bfloat16 g_ch[XE], g_cl[XE];
__device__ unsigned char g_mask[NB * NPAD * NPAD];
__device__ int g_mask_mode;

// ---------------- helpers ---------------------------------------------------
__device__ __forceinline__ uint32_t smem_u32(const void* p) {
    return (uint32_t)__cvta_generic_to_shared(p);
}
__device__ __forceinline__ void ldsm4(uint32_t a, uint32_t& r0, uint32_t& r1,
                                      uint32_t& r2, uint32_t& r3) {
    asm volatile("ldmatrix.sync.aligned.m8n8.x4.shared.b16 {%0,%1,%2,%3},[%4];"
                 : "=r"(r0), "=r"(r1), "=r"(r2), "=r"(r3) : "r"(a));
}
__device__ __forceinline__ void ldsm4t(uint32_t a, uint32_t& r0, uint32_t& r1,
                                       uint32_t& r2, uint32_t& r3) {
    asm volatile("ldmatrix.sync.aligned.m8n8.x4.trans.shared.b16 {%0,%1,%2,%3},[%4];"
                 : "=r"(r0), "=r"(r1), "=r"(r2), "=r"(r3) : "r"(a));
}
__device__ __forceinline__ void mma_bf(float* c, const uint32_t* a, uint32_t b0, uint32_t b1) {
    asm volatile(
        "mma.sync.aligned.m16n8k16.row.col.f32.bf16.bf16.f32 "
        "{%0,%1,%2,%3},{%4,%5,%6,%7},{%8,%9},{%0,%1,%2,%3};"
        : "+f"(c[0]), "+f"(c[1]), "+f"(c[2]), "+f"(c[3])
        : "r"(a[0]), "r"(a[1]), "r"(a[2]), "r"(a[3]), "r"(b0), "r"(b1));
}
__device__ __forceinline__ void packsplit(float a, float b, uint32_t& hi, uint32_t& lo) {
    __nv_bfloat16 ha = __float2bfloat16(a), hb = __float2bfloat16(b);
    __nv_bfloat16 la = __float2bfloat16(a - __bfloat162float(ha));
    __nv_bfloat16 lb = __float2bfloat16(b - __bfloat162float(hb));
    __nv_bfloat162 H = __halves2bfloat162(ha, hb), L = __halves2bfloat162(la, lb);
    hi = *(uint32_t*)&H; lo = *(uint32_t*)&L;
}
__device__ __forceinline__ float fast_exp(float x) {
    float y = fmaxf(x, -60.0f) * 1.44269504f;
    float t = y + 12582912.0f;
    int n = __float_as_int(t) - 0x4B400000;
    float f = y - (t - 12582912.0f);
    float r = 1.54026459e-4f;
    r = fmaf(r, f, 1.33335581e-3f);
    r = fmaf(r, f, 9.61812910e-3f);
    r = fmaf(r, f, 5.55041087e-2f);
    r = fmaf(r, f, 2.40226507e-1f);
    r = fmaf(r, f, 6.93147181e-1f);
    r = fmaf(r, f, 1.0f);
    return __int_as_float(__float_as_int(r) + (n << 23));
}

// ---------------- mask normalize --------------------------------------------
__global__ void mask_detect_kernel(const unsigned int* __restrict__ pm) {
    int t = threadIdx.x;
    bool aF = true, aI = true;
    for (int i = t; i < 4096; i += 32) {
        unsigned int w = pm[i];
        if (!(w == 0u || w == 0x3F800000u)) aF = false;
        if (w > 1u) aI = false;
    }
    aF = __all_sync(0xffffffffu, aF);
    aI = __all_sync(0xffffffffu, aI);
    if (t == 0) g_mask_mode = aF ? 0 : (aI ? 1 : 2);
}
__global__ __launch_bounds__(256) void mask_convert_kernel(const void* __restrict__ pm) {
    const int mode = g_mask_mode;
    const size_t n = (size_t)NB * NPAD * NPAD;
    const size_t stride = (size_t)gridDim.x * blockDim.x;
    for (size_t i = (size_t)blockIdx.x * blockDim.x + threadIdx.x; i < n; i += stride) {
        unsigned char v;
        if (mode == 0)      v = (((const float*)pm)[i] != 0.f) ? 1 : 0;
        else if (mode == 1) v = (((const int*)pm)[i] != 0) ? 1 : 0;
        else                v = (((const unsigned char*)pm)[i] != 0) ? 1 : 0;
        g_mask[i] = v;
    }
}

// ---------------- fp32 -> bf16 hi/lo split ----------------------------------
__global__ __launch_bounds__(256) void split_kernel(const float4* __restrict__ src,
                                                    uint32_t* __restrict__ h,
                                                    uint32_t* __restrict__ l,
                                                    int n4) {
    int i = blockIdx.x * 256 + threadIdx.x;
    if (i >= n4) return;
    float4 v = src[i];
    uint32_t h0, l0, h1, l1;
    packsplit(v.x, v.y, h0, l0);
    packsplit(v.z, v.w, h1, l1);
    h[2 * i] = h0; h[2 * i + 1] = h1;
    l[2 * i] = l0; l[2 * i + 1] = l1;
}

// ---------------- GEMM: C = A @ W^T + b  (split-bf16, 3-mma) -----------------
template <int SPLIT>
__global__ __launch_bounds__(128) void gemm_mma(
    const __nv_bfloat16* __restrict__ Agh, const __nv_bfloat16* __restrict__ Agl,
    const __nv_bfloat16* __restrict__ Wh, const __nv_bfloat16* __restrict__ Wl,
    const float* __restrict__ bias,
    __nv_bfloat16* __restrict__ Oh, __nv_bfloat16* __restrict__ Ol,
    float* __restrict__ Of)
{
    __shared__ __align__(16) __nv_bfloat16 Ah[64][72], Al[64][72];
    __shared__ __align__(16) __nv_bfloat16 Bh[64][72], Bl[64][72];
    const int m0 = blockIdx.x * 64, n0 = blockIdx.y * 64;
    const int t = threadIdx.x, warp = t >> 5, lane = t & 31;
    const int g = lane >> 2, qd = lane & 3;

    float c[8][4];
#pragma unroll
    for (int i = 0; i < 8; i++)
#pragma unroll
        for (int j = 0; j < 4; j++) c[i][j] = 0.f;

    const int lrow = t >> 1, lcb = (t & 1) << 5;
    const int gmr = m0 + lrow;
    const bool mv = gmr < MROWS;
    const size_t aB = (size_t)(mv ? gmr : 0) * EM + lcb;
    const size_t bB = (size_t)(n0 + lrow) * EM + lcb;
    const uint32_t sAh = smem_u32(Ah), sAl = smem_u32(Al);
    const uint32_t sBh = smem_u32(Bh), sBl = smem_u32(Bl);
    const uint32_t aOff = (uint32_t)(((warp * 16 + (lane & 15)) * 72 + ((lane >> 4) << 3)) * 2);
    const uint32_t bOff = (uint32_t)((((lane & 7) + ((lane >> 4) << 3)) * 72 +
                                      (((lane >> 3) & 1) << 3)) * 2);
    const uint4 z4 = make_uint4(0, 0, 0, 0);

    for (int k0 = 0; k0 < EM; k0 += 64) {
        __syncthreads();
#pragma unroll
        for (int i = 0; i < 4; i++) {
            *(uint4*)&Ah[lrow][lcb + i * 8] = mv ? *(const uint4*)(Agh + aB + k0 + i * 8) : z4;
            *(uint4*)&Al[lrow][lcb + i * 8] = mv ? *(const uint4*)(Agl + aB + k0 + i * 8) : z4;
            *(uint4*)&Bh[lrow][lcb + i * 8] = *(const uint4*)(Wh + bB + k0 + i * 8);
            *(uint4*)&Bl[lrow][lcb + i * 8] = *(const uint4*)(Wl + bB + k0 + i * 8);
        }
        __syncthreads();
#pragma unroll
        for (int ks = 0; ks < 4; ks++) {
            uint32_t ah[4], al[4];
            ldsm4(sAh + aOff + ks * 32, ah[0], ah[1], ah[2], ah[3]);
            ldsm4(sAl + aOff + ks * 32, al[0], al[1], al[2], al[3]);
#pragma unroll
            for (int np = 0; np < 4; np++) {
                uint32_t bh4[4], bl4[4];
                ldsm4(sBh + bOff + np * 2304 + ks * 32, bh4[0], bh4[1], bh4[2], bh4[3]);
                ldsm4(sBl + bOff + np * 2304 + ks * 32, bl4[0], bl4[1], bl4[2], bl4[3]);
                mma_bf(c[2 * np], ah, bh4[0], bh4[1]);
                mma_bf(c[2 * np], ah, bl4[0], bl4[1]);
                mma_bf(c[2 * np], al, bh4[0], bh4[1]);
                mma_bf(c[2 * np + 1], ah, bh4[2], bh4[3]);
                mma_bf(c[2 * np + 1], ah, bl4[2], bl4[3]);
                mma_bf(c[2 * np + 1], al, bh4[2], bh4[3]);
            }
        }
    }

    const int r0g = m0 + warp * 16 + g, r1g = r0g + 8;
#pragma unroll
    for (int nt = 0; nt < 8; nt++) {
        const int cn = n0 + nt * 8 + 2 * qd;
        const float bx = __ldg(bias + cn), by = __ldg(bias + cn + 1);
        if (SPLIT) {
            uint32_t hi, lo;
            if (r0g < MROWS) {
                packsplit(c[nt][0] + bx, c[nt][1] + by, hi, lo);
                *(uint32_t*)(Oh + (size_t)r0g * EM + cn) = hi;
                *(uint32_t*)(Ol + (size_t)r0g * EM + cn) = lo;
            }
            if (r1g < MROWS) {
                packsplit(c[nt][2] + bx, c[nt][3] + by, hi, lo);
                *(uint32_t*)(Oh + (size_t)r1g * EM + cn) = hi;
                *(uint32_t*)(Ol + (size_t)r1g * EM + cn) = lo;
            }
        } else {
            if (r0g < MROWS)
                *(float2*)(Of + (size_t)r0g * EM + cn) = make_float2(c[nt][0] + bx, c[nt][1] + by);
            if (r1g < MROWS)
                *(float2*)(Of + (size_t)r1g * EM + cn) = make_float2(c[nt][2] + bx, c[nt][3] + by);
        }
    }
}

// ---------------- flash attention: mma S + register-P + mma PV ---------------
__global__ __launch_bounds__(128) void attn_mma(const float* __restrict__ abias) {
    __shared__ __align__(16) __nv_bfloat16 Qh[64][72], Ql[64][72];
    __shared__ __align__(16) __nv_bfloat16 Kh[32][72], Kl[32][72];
    __shared__ __align__(16) __nv_bfloat16 Vh[32][72], Vl[32][72];

    const int bh = blockIdx.y;
    const int b = bh >> 3, h = bh & 7;
    const int q0 = blockIdx.x * 64;
    const int t = threadIdx.x, warp = t >> 5, lane = t & 31;
    const int g = lane >> 2, qd = lane & 3;
    const uint4 z4 = make_uint4(0, 0, 0, 0);

    // ---- load Q tile (64 rows x 64 head dims) ----
    {
        const int row = t >> 1, cb = (t & 1) << 5;
        const int gq = q0 + row;
        const bool v = gq < NP_;
        const size_t base = (size_t)(b * NP_ + (v ? gq : 0)) * EM + h * DH + cb;
#pragma unroll
        for (int i = 0; i < 4; i++) {
            *(uint4*)&Qh[row][cb + i * 8] = v ? *(const uint4*)(g_qh + base + i * 8) : z4;
            *(uint4*)&Ql[row][cb + i * 8] = v ? *(const uint4*)(g_ql + base + i * 8) : z4;
        }
    }

    const uint32_t sQh = smem_u32(Qh), sQl = smem_u32(Ql);
    const uint32_t sKh = smem_u32(Kh), sKl = smem_u32(Kl);
    const uint32_t sVh = smem_u32(Vh), sVl = smem_u32(Vl);
    const uint32_t qOff = (uint32_t)(((warp * 16 + (lane & 15)) * 72 + ((lane >> 4) << 3)) * 2);
    const uint32_t kOff = (uint32_t)((((lane & 7) + ((lane >> 4) << 3)) * 72 +
                                      (((lane >> 3) & 1) << 3)) * 2);
    const uint32_t vOff = (uint32_t)((((lane & 7) + (((lane >> 3) & 1) << 3)) * 72 +
                                      ((lane >> 4) << 3)) * 2);

    const int gq0 = q0 + warp * 16 + g, gq1 = gq0 + 8;
    // ALL row indices clamped into bounds (speculation + padding safe)
    const int bq0 = min(gq0, NP_ - 1), bq1 = min(gq1, NP_ - 1);
    const int mq0 = min(gq0 > 0 ? gq0 - 1 : 0, NPAD - 1);
    const int mq1 = min(gq1 - 1, NPAD - 1);
    const float* brow0 = abias + ((size_t)bh * NP_ + bq0) * NP_;
    const float* brow1 = abias + ((size_t)bh * NP_ + bq1) * NP_;
    const unsigned char* mrow0 = g_mask + ((size_t)b * NPAD + mq0) * NPAD;
    const unsigned char* mrow1 = g_mask + ((size_t)b * NPAD + mq1) * NPAD;

    float m0 = -1e30f, m1 = -1e30f, l0 = 0.f, l1 = 0.f;
    float o[8][4];
#pragma unroll
    for (int i = 0; i < 8; i++)
#pragma unroll
        for (int j = 0; j < 4; j++) o[i][j] = 0.f;

    for (int kt = 0; kt < 33; kt++) {
        const int kb = kt * 32;
        __syncthreads();
        // ---- load K,V tiles (32 keys x 64 dims) ----
        {
            const int row = t >> 2, cb = (t & 3) << 4;
            const int gk = kb + row;
            const bool v = gk < NP_;
            const size_t base = (size_t)(b * NP_ + (v ? gk : 0)) * EM + h * DH + cb;
#pragma unroll
            for (int i = 0; i < 2; i++) {
                *(uint4*)&Kh[row][cb + i * 8] = v ? *(const uint4*)(g_kh + base + i * 8) : z4;
                *(uint4*)&Kl[row][cb + i * 8] = v ? *(const uint4*)(g_kl + base + i * 8) : z4;
                *(uint4*)&Vh[row][cb + i * 8] = v ? *(const uint4*)(g_vh + base + i * 8) : z4;
                *(uint4*)&Vl[row][cb + i * 8] = v ? *(const uint4*)(g_vl + base + i * 8) : z4;
            }
        }
        __syncthreads();

        // ---- S = Q K^T  (16 x 32 per warp) ----
        float s[4][4];
#pragma unroll
        for (int i = 0; i < 4; i++)
#pragma unroll
            for (int j = 0; j < 4; j++) s[i][j] = 0.f;
#pragma unroll
        for (int ks = 0; ks < 4; ks++) {
            uint32_t ah[4], al[4];
            ldsm4(sQh + qOff + ks * 32, ah[0], ah[1], ah[2], ah[3]);
            ldsm4(sQl + qOff + ks * 32, al[0], al[1], al[2], al[3]);
#pragma unroll
            for (int np = 0; np < 2; np++) {
                uint32_t bh4[4], bl4[4];
                ldsm4(sKh + kOff + np * 2304 + ks * 32, bh4[0], bh4[1], bh4[2], bh4[3]);
                ldsm4(sKl + kOff + np * 2304 + ks * 32, bl4[0], bl4[1], bl4[2], bl4[3]);
                mma_bf(s[2 * np], ah, bh4[0], bh4[1]);
                mma_bf(s[2 * np], ah, bl4[0], bl4[1]);
                mma_bf(s[2 * np], al, bh4[0], bh4[1]);
                mma_bf(s[2 * np + 1], ah, bh4[2], bh4[3]);
                mma_bf(s[2 * np + 1], ah, bl4[2], bl4[3]);
                mma_bf(s[2 * np + 1], al, bh4[2], bh4[3]);
            }
        }

        // ---- scale + bias + pad-mask (all indices clamped: speculation-safe) ----
#pragma unroll
        for (int nt = 0; nt < 4; nt++) {
            const int gk0 = kb + nt * 8 + 2 * qd, gk1 = gk0 + 1;
            const int mc0 = min(max(gk0 - 1, 0), NPAD - 1);
            const int mc1 = min(gk1 - 1, NPAD - 1);
            const int bc0 = min(gk0, NP_ - 1), bc1 = min(gk1, NP_ - 1);
            const unsigned char u00 = mrow0[mc0], u01 = mrow0[mc1];
            const unsigned char u10 = mrow1[mc0], u11 = mrow1[mc1];
            bool ok;
            ok = gk0 < NP_ && (gq0 == 0 || gk0 == 0 || u00);
            s[nt][0] = ok ? fmaf(s[nt][0], 0.125f, __ldg(brow0 + bc0)) : -1e30f;
            ok = gk1 < NP_ && (gq0 == 0 || u01);
            s[nt][1] = ok ? fmaf(s[nt][1], 0.125f, __ldg(brow0 + bc1)) : -1e30f;
            ok = gk0 < NP_ && (gq1 == 0 || gk0 == 0 || u10);
            s[nt][2] = ok ? fmaf(s[nt][2], 0.125f, __ldg(brow1 + bc0)) : -1e30f;
            ok = gk1 < NP_ && (gq1 == 0 || u11);
            s[nt][3] = ok ? fmaf(s[nt][3], 0.125f, __ldg(brow1 + bc1)) : -1e30f;
        }

        // ---- online softmax (quad-wide reduce) ----
        float lm0 = -1e30f, lm1 = -1e30f;
#pragma unroll
        for (int nt = 0; nt < 4; nt++) {
            lm0 = fmaxf(lm0, fmaxf(s[nt][0], s[nt][1]));
            lm1 = fmaxf(lm1, fmaxf(s[nt][2], s[nt][3]));
        }
        lm0 = fmaxf(lm0, __shfl_xor_sync(0xffffffffu, lm0, 1));
        lm0 = fmaxf(lm0, __shfl_xor_sync(0xffffffffu, lm0, 2));
        lm1 = fmaxf(lm1, __shfl_xor_sync(0xffffffffu, lm1, 1));
        lm1 = fmaxf(lm1, __shfl_xor_sync(0xffffffffu, lm1, 2));
        const float mn0 = fmaxf(m0, lm0), mn1 = fmaxf(m1, lm1);
        const float sc0 = fast_exp(m0 - mn0), sc1 = fast_exp(m1 - mn1);
        m0 = mn0; m1 = mn1;

        float ps0 = 0.f, ps1 = 0.f;
#pragma unroll
        for (int nt = 0; nt < 4; nt++) {
            s[nt][0] = fast_exp(s[nt][0] - mn0);
            s[nt][1] = fast_exp(s[nt][1] - mn0);
            s[nt][2] = fast_exp(s[nt][2] - mn1);
            s[nt][3] = fast_exp(s[nt][3] - mn1);
            ps0 += s[nt][0] + s[nt][1];
            ps1 += s[nt][2] + s[nt][3];
        }
        ps0 += __shfl_xor_sync(0xffffffffu, ps0, 1);
        ps0 += __shfl_xor_sync(0xffffffffu, ps0, 2);
        ps1 += __shfl_xor_sync(0xffffffffu, ps1, 1);
        ps1 += __shfl_xor_sync(0xffffffffu, ps1, 2);
        l0 = l0 * sc0 + ps0;
        l1 = l1 * sc1 + ps1;

        // ---- pack P (C-frag == A-frag layout), rescale O ----
        uint32_t aph[2][4], apl[2][4];
#pragma unroll
        for (int ks = 0; ks < 2; ks++) {
            packsplit(s[2 * ks][0], s[2 * ks][1], aph[ks][0], apl[ks][0]);
            packsplit(s[2 * ks][2], s[2 * ks][3], aph[ks][1], apl[ks][1]);
            packsplit(s[2 * ks + 1][0], s[2 * ks + 1][1], aph[ks][2], apl[ks][2]);
            packsplit(s[2 * ks + 1][2], s[2 * ks + 1][3], aph[ks][3], apl[ks][3]);
        }
#pragma unroll
        for (int nt = 0; nt < 8; nt++) {
            o[nt][0] *= sc0; o[nt][1] *= sc0;
            o[nt][2] *= sc1; o[nt][3] *= sc1;
        }

        // ---- O += P V ----
#pragma unroll
        for (int ks = 0; ks < 2; ks++) {
#pragma unroll
            for (int dp = 0; dp < 4; dp++) {
                uint32_t bh4[4], bl4[4];
                ldsm4t(sVh + vOff + ks * 2304 + dp * 32, bh4[0], bh4[1], bh4[2], bh4[3]);
                ldsm4t(sVl + vOff + ks * 2304 + dp * 32, bl4[0], bl4[1], bl4[2], bl4[3]);
                mma_bf(o[2 * dp], aph[ks], bh4[0], bh4[1]);
                mma_bf(o[2 * dp], aph[ks], bl4[0], bl4[1]);
                mma_bf(o[2 * dp], apl[ks], bh4[0], bh4[1]);
                mma_bf(o[2 * dp + 1], aph[ks], bh4[2], bh4[3]);
                mma_bf(o[2 * dp + 1], aph[ks], bl4[2], bl4[3]);
                mma_bf(o[2 * dp + 1], apl[ks], bh4[2], bh4[3]);
            }
        }
    }

    // ---- finalize: ctx = O / l, split-bf16 write ----
    const float i0 = (l0 > 0.f) ? 1.f / l0 : 0.f;
    const float i1 = (l1 > 0.f) ? 1.f / l1 : 0.f;
#pragma unroll
    for (int nt = 0; nt < 8; nt++) {
        const int d0 = h * DH + nt * 8 + 2 * qd;
        uint32_t hi, lo;
        if (gq0 < NP_) {
            packsplit(o[nt][0] * i0, o[nt][1] * i0, hi, lo);
            const size_t off = (size_t)(b * NP_ + gq0) * EM + d0;
            *(uint32_t*)(g_ch + off) = hi; *(uint32_t*)(g_cl + off) = lo;
        }
        if (gq1 < NP_) {
            packsplit(o[nt][2] * i1, o[nt][3] * i1, hi, lo);
            const size_t off = (size_t)(b * NP_ + gq1) * EM + d0;
            *(uint32_t*)(g_ch + off) = hi; *(uint32_t*)(g_cl + off) = lo;
        }
    }
}

// ---------------------------------------------------------------------------
extern "C" void kernel_launch(void* const* d_in, const int* in_sizes, int n_in,
                              void* d_out, int out_size)
{
    const float* x = (const float*)d_in[0];
    const float* abias = (const float*)d_in[1];
    const void* pmask = (const void*)d_in[2];
    const float* Ws[4] = {(const float*)d_in[3], (const float*)d_in[5],
                          (const float*)d_in[7], (const float*)d_in[9]};
    const float* bs[4] = {(const float*)d_in[4], (const float*)d_in[6],
                          (const float*)d_in[8], (const float*)d_in[10]};
    float* out = (float*)d_out;

    void *xh, *xl, *wh, *wl, *qh, *ql, *kh, *kl, *vh, *vl, *ch, *cl;
    cudaGetSymbolAddress(&xh, g_xh); cudaGetSymbolAddress(&xl, g_xl);
    cudaGetSymbolAddress(&wh, g_wh); cudaGetSymbolAddress(&wl, g_wl);
    cudaGetSymbolAddress(&qh, g_qh); cudaGetSymbolAddress(&ql, g_ql);
    cudaGetSymbolAddress(&kh, g_kh); cudaGetSymbolAddress(&kl, g_kl);
    cudaGetSymbolAddress(&vh, g_vh); cudaGetSymbolAddress(&vl, g_vl);
    cudaGetSymbolAddress(&ch, g_ch); cudaGetSymbolAddress(&cl, g_cl);

    mask_detect_kernel<<<1, 32>>>((const unsigned int*)pmask);
    mask_convert_kernel<<<1024, 256>>>(pmask);

    split_kernel<<<(XE / 4 + 255) / 256, 256>>>((const float4*)x,
        (uint32_t*)xh, (uint32_t*)xl, XE / 4);
    for (int i = 0; i < 4; i++)
        split_kernel<<<WE / 4 / 256, 256>>>((const float4*)Ws[i],
            (uint32_t*)((__nv_bfloat16*)wh + (size_t)i * WE),
            (uint32_t*)((__nv_bfloat16*)wl + (size_t)i * WE), WE / 4);

    dim3 gg(129, 8);
    gemm_mma<1><<<gg, 128>>>((const __nv_bfloat16*)xh, (const __nv_bfloat16*)xl,
        (const __nv_bfloat16*)wh, (const __nv_bfloat16*)wl, bs[0],
        (__nv_bfloat16*)qh, (__nv_bfloat16*)ql, nullptr);
    gemm_mma<1><<<gg, 128>>>((const __nv_bfloat16*)xh, (const __nv_bfloat16*)xl,
        (const __nv_bfloat16*)wh + (size_t)1 * WE, (const __nv_bfloat16*)wl + (size_t)1 * WE, bs[1],
        (__nv_bfloat16*)kh, (__nv_bfloat16*)kl, nullptr);
    gemm_mma<1><<<gg, 128>>>((const __nv_bfloat16*)xh, (const __nv_bfloat16*)xl,
        (const __nv_bfloat16*)wh + (size_t)2 * WE, (const __nv_bfloat16*)wl + (size_t)2 * WE, bs[2],
        (__nv_bfloat16*)vh, (__nv_bfloat16*)vl, nullptr);

    attn_mma<<<dim3(17, 64), 128>>>(abias);

    gemm_mma<0><<<gg, 128>>>((const __nv_bfloat16*)ch, (const __nv_bfloat16*)cl,
        (const __nv_bfloat16*)wh + (size_t)3 * WE, (const __nv_bfloat16*)wl + (size_t)3 * WE, bs[3],
        nullptr, nullptr, out);
}

// round 10
// speedup vs baseline: 3.4793x; 1.0499x over previous
#include <cuda_runtime.h>
#include <cuda_bf16.h>
#include <math.h>
#include <stdint.h>

#define NB 8
#define NH 8
#define NP_ 1025
#define NPAD 1024
#define DH 64
#define EM 512
#define MROWS (NB * NP_)      // 8200
#define XE (MROWS * EM)       // 4198400
#define WE (EM * EM)          // 262144

__device__ __align__(16) __nv_bfloat16 g_xh[XE], g_xl[XE];
__device__ __align__(16) __nv_bfloat16 g_wh[4][WE], g_wl[4][WE];
__device__ __align__(16) __nv_bfloat16 g_qh[XE], g_ql[XE];
__device__ __align__(16) __nv_bfloat16 g_kh[XE], g_kl[XE];
__device__ __align__(16) __nv_bfloat16 g_vh[XE], g_vl[XE];
__device__ __align__(16) __nv_bfloat16 g_ch[XE], g_cl[XE];
__device__ unsigned char g_mask[NB * NPAD * NPAD];
__device__ int g_mask_mode;

// ---------------- helpers ---------------------------------------------------
__device__ __forceinline__ uint32_t smem_u32(const void* p) {
    return (uint32_t)__cvta_generic_to_shared(p);
}
__device__ __forceinline__ void ldsm4(uint32_t a, uint32_t& r0, uint32_t& r1,
                                      uint32_t& r2, uint32_t& r3) {
    asm volatile("ldmatrix.sync.aligned.m8n8.x4.shared.b16 {%0,%1,%2,%3},[%4];"
                 : "=r"(r0), "=r"(r1), "=r"(r2), "=r"(r3) : "r"(a));
}
__device__ __forceinline__ void ldsm4t(uint32_t a, uint32_t& r0, uint32_t& r1,
                                       uint32_t& r2, uint32_t& r3) {
    asm volatile("ldmatrix.sync.aligned.m8n8.x4.trans.shared.b16 {%0,%1,%2,%3},[%4];"
                 : "=r"(r0), "=r"(r1), "=r"(r2), "=r"(r3) : "r"(a));
}
__device__ __forceinline__ void mma_bf(float* c, const uint32_t* a, uint32_t b0, uint32_t b1) {
    asm volatile(
        "mma.sync.aligned.m16n8k16.row.col.f32.bf16.bf16.f32 "
        "{%0,%1,%2,%3},{%4,%5,%6,%7},{%8,%9},{%0,%1,%2,%3};"
        : "+f"(c[0]), "+f"(c[1]), "+f"(c[2]), "+f"(c[3])
        : "r"(a[0]), "r"(a[1]), "r"(a[2]), "r"(a[3]), "r"(b0), "r"(b1));
}
__device__ __forceinline__ void packsplit(float a, float b, uint32_t& hi, uint32_t& lo) {
    __nv_bfloat16 ha = __float2bfloat16(a), hb = __float2bfloat16(b);
    __nv_bfloat16 la = __float2bfloat16(a - __bfloat162float(ha));
    __nv_bfloat16 lb = __float2bfloat16(b - __bfloat162float(hb));
    __nv_bfloat162 H = __halves2bfloat162(ha, hb), L = __halves2bfloat162(la, lb);
    hi = *(uint32_t*)&H; lo = *(uint32_t*)&L;
}
__device__ __forceinline__ float fast_exp(float x) {
    float y = fmaxf(x, -60.0f) * 1.44269504f;
    float t = y + 12582912.0f;
    int n = __float_as_int(t) - 0x4B400000;
    float f = y - (t - 12582912.0f);
    float r = 1.54026459e-4f;
    r = fmaf(r, f, 1.33335581e-3f);
    r = fmaf(r, f, 9.61812910e-3f);
    r = fmaf(r, f, 5.55041087e-2f);
    r = fmaf(r, f, 2.40226507e-1f);
    r = fmaf(r, f, 6.93147181e-1f);
    r = fmaf(r, f, 1.0f);
    return __int_as_float(__float_as_int(r) + (n << 23));
}
__device__ __forceinline__ void cpa16(uint32_t dst, const void* src, int sz) {
    asm volatile("cp.async.cg.shared.global [%0], [%1], 16, %2;"
                 :: "r"(dst), "l"(src), "r"(sz));
}
__device__ __forceinline__ void cpa_commit() {
    asm volatile("cp.async.commit_group;");
}
template <int N> __device__ __forceinline__ void cpa_wait() {
    asm volatile("cp.async.wait_group %0;" :: "n"(N));
}

// ---------------- mask normalize --------------------------------------------
__global__ void mask_detect_kernel(const unsigned int* __restrict__ pm) {
    int t = threadIdx.x;
    bool aF = true, aI = true;
    for (int i = t; i < 4096; i += 32) {
        unsigned int w = pm[i];
        if (!(w == 0u || w == 0x3F800000u)) aF = false;
        if (w > 1u) aI = false;
    }
    aF = __all_sync(0xffffffffu, aF);
    aI = __all_sync(0xffffffffu, aI);
    if (t == 0) g_mask_mode = aF ? 0 : (aI ? 1 : 2);
}
__global__ __launch_bounds__(256) void mask_convert_kernel(const void* __restrict__ pm) {
    const int mode = g_mask_mode;
    const size_t n = (size_t)NB * NPAD * NPAD;
    const size_t stride = (size_t)gridDim.x * blockDim.x;
    for (size_t i = (size_t)blockIdx.x * blockDim.x + threadIdx.x; i < n; i += stride) {
        unsigned char v;
        if (mode == 0)      v = (((const float*)pm)[i] != 0.f) ? 1 : 0;
        else if (mode == 1) v = (((const int*)pm)[i] != 0) ? 1 : 0;
        else                v = (((const unsigned char*)pm)[i] != 0) ? 1 : 0;
        g_mask[i] = v;
    }
}

// ---------------- fp32 -> bf16 hi/lo split ----------------------------------
__global__ __launch_bounds__(256) void split_kernel(const float4* __restrict__ src,
                                                    uint32_t* __restrict__ h,
                                                    uint32_t* __restrict__ l,
                                                    int n4) {
    int i = blockIdx.x * 256 + threadIdx.x;
    if (i >= n4) return;
    float4 v = src[i];
    uint32_t h0, l0, h1, l1;
    packsplit(v.x, v.y, h0, l0);
    packsplit(v.z, v.w, h1, l1);
    h[2 * i] = h0; h[2 * i + 1] = h1;
    l[2 * i] = l0; l[2 * i + 1] = l1;
}

// ---------------- GEMM: C = A @ W^T + b  (split-bf16, cp.async 2-stage) ------
// dynamic smem: 2 stages x (Ah,Al,Bh,Bl each 64x72 bf16 = 9216 B) = 73728 B
#define G_STG 36864
template <int SPLIT>
__global__ __launch_bounds__(128) void gemm_mma(
    const __nv_bfloat16* __restrict__ Agh, const __nv_bfloat16* __restrict__ Agl,
    const __nv_bfloat16* __restrict__ Wh, const __nv_bfloat16* __restrict__ Wl,
    const float* __restrict__ bias,
    __nv_bfloat16* __restrict__ Oh, __nv_bfloat16* __restrict__ Ol,
    float* __restrict__ Of)
{
    extern __shared__ __align__(16) char dsm[];
    const uint32_t dbase = smem_u32(dsm);
    const int m0 = blockIdx.x * 64, n0 = blockIdx.y * 64;
    const int t = threadIdx.x, warp = t >> 5, lane = t & 31;
    const int g = lane >> 2, qd = lane & 3;

    float c[8][4];
#pragma unroll
    for (int i = 0; i < 8; i++)
#pragma unroll
        for (int j = 0; j < 4; j++) c[i][j] = 0.f;

    const int lrow = t >> 1, lcb = (t & 1) << 5;
    const int gmr = m0 + lrow;
    const bool mv = gmr < MROWS;
    const size_t aB = (size_t)(mv ? gmr : 0) * EM + lcb;
    const size_t bB = (size_t)(n0 + lrow) * EM + lcb;
    const uint32_t offA = (uint32_t)((lrow * 72 + lcb) * 2);
    const int asz = mv ? 16 : 0;
    const uint32_t aOff = (uint32_t)(((warp * 16 + (lane & 15)) * 72 + ((lane >> 4) << 3)) * 2);
    const uint32_t bOff = (uint32_t)((((lane & 7) + ((lane >> 4) << 3)) * 72 +
                                      (((lane >> 3) & 1) << 3)) * 2);

#define G_ISSUE(k0, s) do {                                                     \
        const uint32_t sb_ = dbase + (s) * G_STG;                               \
        _Pragma("unroll")                                                       \
        for (int i_ = 0; i_ < 4; i_++) {                                        \
            cpa16(sb_ + offA + i_ * 16,          Agh + aB + (k0) + i_ * 8, asz);\
            cpa16(sb_ + 9216 + offA + i_ * 16,   Agl + aB + (k0) + i_ * 8, asz);\
            cpa16(sb_ + 18432 + offA + i_ * 16,  Wh + bB + (k0) + i_ * 8, 16);  \
            cpa16(sb_ + 27648 + offA + i_ * 16,  Wl + bB + (k0) + i_ * 8, 16);  \
        }                                                                       \
        cpa_commit();                                                           \
    } while (0)

    G_ISSUE(0, 0);
    G_ISSUE(64, 1);

    for (int ki = 0; ki < 8; ki++) {
        cpa_wait<1>();
        __syncthreads();
        const uint32_t sb = dbase + (ki & 1) * G_STG;
        const uint32_t sAh = sb, sAl = sb + 9216, sBh = sb + 18432, sBl = sb + 27648;
#pragma unroll
        for (int ks = 0; ks < 4; ks++) {
            uint32_t ah[4], al[4];
            ldsm4(sAh + aOff + ks * 32, ah[0], ah[1], ah[2], ah[3]);
            ldsm4(sAl + aOff + ks * 32, al[0], al[1], al[2], al[3]);
#pragma unroll
            for (int np = 0; np < 4; np++) {
                uint32_t bh4[4], bl4[4];
                ldsm4(sBh + bOff + np * 2304 + ks * 32, bh4[0], bh4[1], bh4[2], bh4[3]);
                ldsm4(sBl + bOff + np * 2304 + ks * 32, bl4[0], bl4[1], bl4[2], bl4[3]);
                mma_bf(c[2 * np], ah, bh4[0], bh4[1]);
                mma_bf(c[2 * np], ah, bl4[0], bl4[1]);
                mma_bf(c[2 * np], al, bh4[0], bh4[1]);
                mma_bf(c[2 * np + 1], ah, bh4[2], bh4[3]);
                mma_bf(c[2 * np + 1], ah, bl4[2], bl4[3]);
                mma_bf(c[2 * np + 1], al, bh4[2], bh4[3]);
            }
        }
        __syncthreads();
        if (ki + 2 < 8) { G_ISSUE((ki + 2) * 64, ki & 1); }
        else cpa_commit();
    }

    const int r0g = m0 + warp * 16 + g, r1g = r0g + 8;
#pragma unroll
    for (int nt = 0; nt < 8; nt++) {
        const int cn = n0 + nt * 8 + 2 * qd;
        const float bx = __ldg(bias + cn), by = __ldg(bias + cn + 1);
        if (SPLIT) {
            uint32_t hi, lo;
            if (r0g < MROWS) {
                packsplit(c[nt][0] + bx, c[nt][1] + by, hi, lo);
                *(uint32_t*)(Oh + (size_t)r0g * EM + cn) = hi;
                *(uint32_t*)(Ol + (size_t)r0g * EM + cn) = lo;
            }
            if (r1g < MROWS) {
                packsplit(c[nt][2] + bx, c[nt][3] + by, hi, lo);
                *(uint32_t*)(Oh + (size_t)r1g * EM + cn) = hi;
                *(uint32_t*)(Ol + (size_t)r1g * EM + cn) = lo;
            }
        } else {
            if (r0g < MROWS)
                *(float2*)(Of + (size_t)r0g * EM + cn) = make_float2(c[nt][0] + bx, c[nt][1] + by);
            if (r1g < MROWS)
                *(float2*)(Of + (size_t)r1g * EM + cn) = make_float2(c[nt][2] + bx, c[nt][3] + by);
        }
    }
#undef G_ISSUE
}

// ---------------- flash attention: Q-frag hoist + cp.async 2-stage K/V -------
// dynamic smem: Qh,Ql (2 x 9216) + 2 stages x (Kh,Kl,Vh,Vl each 4608) = 55296 B
#define A_QSZ 18432
#define A_STG 18432
__global__ __launch_bounds__(128) void attn_mma(const float* __restrict__ abias) {
    extern __shared__ __align__(16) char dsm[];
    const uint32_t dbase = smem_u32(dsm);

    const int bh = blockIdx.y;
    const int b = bh >> 3, h = bh & 7;
    const int q0 = blockIdx.x * 64;
    const int t = threadIdx.x, warp = t >> 5, lane = t & 31;
    const int g = lane >> 2, qd = lane & 3;
    const uint4 z4 = make_uint4(0, 0, 0, 0);

    // K/V cp.async mapping
    const int kvrow = t >> 2, kvcb = (t & 3) << 4;
    const uint32_t offKV = (uint32_t)((kvrow * 72 + kvcb) * 2);

#define A_ISSUE(kt, s) do {                                                       \
        const int gk_ = (kt) * 32 + kvrow;                                        \
        const bool v_ = gk_ < NP_;                                                \
        const size_t gb_ = (size_t)(b * NP_ + (v_ ? gk_ : 0)) * EM + h * DH + kvcb;\
        const int sz_ = v_ ? 16 : 0;                                              \
        const uint32_t sb_ = dbase + A_QSZ + (s) * A_STG;                         \
        _Pragma("unroll")                                                         \
        for (int i_ = 0; i_ < 2; i_++) {                                          \
            cpa16(sb_ + offKV + i_ * 16,          g_kh + gb_ + i_ * 8, sz_);      \
            cpa16(sb_ + 4608 + offKV + i_ * 16,   g_kl + gb_ + i_ * 8, sz_);      \
            cpa16(sb_ + 9216 + offKV + i_ * 16,   g_vh + gb_ + i_ * 8, sz_);      \
            cpa16(sb_ + 13824 + offKV + i_ * 16,  g_vl + gb_ + i_ * 8, sz_);      \
        }                                                                         \
        cpa_commit();                                                             \
    } while (0)

    A_ISSUE(0, 0);
    A_ISSUE(1, 1);

    // ---- load Q tile (64 rows x 64 head dims) to smem ----
    {
        const int row = t >> 1, cb = (t & 1) << 5;
        const int gq = q0 + row;
        const bool v = gq < NP_;
        const size_t base = (size_t)(b * NP_ + (v ? gq : 0)) * EM + h * DH + cb;
        char* qh_s = dsm;
        char* ql_s = dsm + 9216;
#pragma unroll
        for (int i = 0; i < 4; i++) {
            *(uint4*)(qh_s + (row * 72 + cb + i * 8) * 2) =
                v ? *(const uint4*)(g_qh + base + i * 8) : z4;
            *(uint4*)(ql_s + (row * 72 + cb + i * 8) * 2) =
                v ? *(const uint4*)(g_ql + base + i * 8) : z4;
        }
    }
    __syncthreads();

    const uint32_t qOff = (uint32_t)(((warp * 16 + (lane & 15)) * 72 + ((lane >> 4) << 3)) * 2);
    const uint32_t kOff = (uint32_t)((((lane & 7) + ((lane >> 4) << 3)) * 72 +
                                      (((lane >> 3) & 1) << 3)) * 2);
    const uint32_t vOff = (uint32_t)((((lane & 7) + (((lane >> 3) & 1) << 3)) * 72 +
                                      ((lane >> 4) << 3)) * 2);

    // ---- hoist Q fragments to registers (loop-invariant) ----
    uint32_t qhf[4][4], qlf[4][4];
#pragma unroll
    for (int ks = 0; ks < 4; ks++) {
        ldsm4(dbase + qOff + ks * 32, qhf[ks][0], qhf[ks][1], qhf[ks][2], qhf[ks][3]);
        ldsm4(dbase + 9216 + qOff + ks * 32, qlf[ks][0], qlf[ks][1], qlf[ks][2], qlf[ks][3]);
    }

    const int gq0 = q0 + warp * 16 + g, gq1 = gq0 + 8;
    const int bq0 = min(gq0, NP_ - 1), bq1 = min(gq1, NP_ - 1);
    const int mq0 = min(gq0 > 0 ? gq0 - 1 : 0, NPAD - 1);
    const int mq1 = min(gq1 - 1, NPAD - 1);
    const float* brow0 = abias + ((size_t)bh * NP_ + bq0) * NP_;
    const float* brow1 = abias + ((size_t)bh * NP_ + bq1) * NP_;
    const unsigned char* mrow0 = g_mask + ((size_t)b * NPAD + mq0) * NPAD;
    const unsigned char* mrow1 = g_mask + ((size_t)b * NPAD + mq1) * NPAD;

    float m0 = -1e30f, m1 = -1e30f, l0 = 0.f, l1 = 0.f;
    float o[8][4];
#pragma unroll
    for (int i = 0; i < 8; i++)
#pragma unroll
        for (int j = 0; j < 4; j++) o[i][j] = 0.f;

    for (int kt = 0; kt < 33; kt++) {
        const int kb = kt * 32;
        cpa_wait<1>();
        __syncthreads();
        const uint32_t sb = dbase + A_QSZ + (kt & 1) * A_STG;
        const uint32_t sKh = sb, sKl = sb + 4608, sVh = sb + 9216, sVl = sb + 13824;

        // ---- S = Q K^T  (16 x 32 per warp) ----
        float s[4][4];
#pragma unroll
        for (int i = 0; i < 4; i++)
#pragma unroll
            for (int j = 0; j < 4; j++) s[i][j] = 0.f;
#pragma unroll
        for (int ks = 0; ks < 4; ks++) {
#pragma unroll
            for (int np = 0; np < 2; np++) {
                uint32_t bh4[4], bl4[4];
                ldsm4(sKh + kOff + np * 2304 + ks * 32, bh4[0], bh4[1], bh4[2], bh4[3]);
                ldsm4(sKl + kOff + np * 2304 + ks * 32, bl4[0], bl4[1], bl4[2], bl4[3]);
                mma_bf(s[2 * np], qhf[ks], bh4[0], bh4[1]);
                mma_bf(s[2 * np], qhf[ks], bl4[0], bl4[1]);
                mma_bf(s[2 * np], qlf[ks], bh4[0], bh4[1]);
                mma_bf(s[2 * np + 1], qhf[ks], bh4[2], bh4[3]);
                mma_bf(s[2 * np + 1], qhf[ks], bl4[2], bl4[3]);
                mma_bf(s[2 * np + 1], qlf[ks], bh4[2], bh4[3]);
            }
        }

        // ---- scale + bias + pad-mask (all indices clamped) ----
#pragma unroll
        for (int nt = 0; nt < 4; nt++) {
            const int gk0 = kb + nt * 8 + 2 * qd, gk1 = gk0 + 1;
            const int mc0 = min(max(gk0 - 1, 0), NPAD - 1);
            const int mc1 = min(gk1 - 1, NPAD - 1);
            const int bc0 = min(gk0, NP_ - 1), bc1 = min(gk1, NP_ - 1);
            const unsigned char u00 = mrow0[mc0], u01 = mrow0[mc1];
            const unsigned char u10 = mrow1[mc0], u11 = mrow1[mc1];
            bool ok;
            ok = gk0 < NP_ && (gq0 == 0 || gk0 == 0 || u00);
            s[nt][0] = ok ? fmaf(s[nt][0], 0.125f, __ldg(brow0 + bc0)) : -1e30f;
            ok = gk1 < NP_ && (gq0 == 0 || u01);
            s[nt][1] = ok ? fmaf(s[nt][1], 0.125f, __ldg(brow0 + bc1)) : -1e30f;
            ok = gk0 < NP_ && (gq1 == 0 || gk0 == 0 || u10);
            s[nt][2] = ok ? fmaf(s[nt][2], 0.125f, __ldg(brow1 + bc0)) : -1e30f;
            ok = gk1 < NP_ && (gq1 == 0 || u11);
            s[nt][3] = ok ? fmaf(s[nt][3], 0.125f, __ldg(brow1 + bc1)) : -1e30f;
        }

        // ---- online softmax (quad-wide reduce) ----
        float lm0 = -1e30f, lm1 = -1e30f;
#pragma unroll
        for (int nt = 0; nt < 4; nt++) {
            lm0 = fmaxf(lm0, fmaxf(s[nt][0], s[nt][1]));
            lm1 = fmaxf(lm1, fmaxf(s[nt][2], s[nt][3]));
        }
        lm0 = fmaxf(lm0, __shfl_xor_sync(0xffffffffu, lm0, 1));
        lm0 = fmaxf(lm0, __shfl_xor_sync(0xffffffffu, lm0, 2));
        lm1 = fmaxf(lm1, __shfl_xor_sync(0xffffffffu, lm1, 1));
        lm1 = fmaxf(lm1, __shfl_xor_sync(0xffffffffu, lm1, 2));
        const float mn0 = fmaxf(m0, lm0), mn1 = fmaxf(m1, lm1);
        const float sc0 = fast_exp(m0 - mn0), sc1 = fast_exp(m1 - mn1);
        m0 = mn0; m1 = mn1;

        float ps0 = 0.f, ps1 = 0.f;
#pragma unroll
        for (int nt = 0; nt < 4; nt++) {
            s[nt][0] = fast_exp(s[nt][0] - mn0);
            s[nt][1] = fast_exp(s[nt][1] - mn0);
            s[nt][2] = fast_exp(s[nt][2] - mn1);
            s[nt][3] = fast_exp(s[nt][3] - mn1);
            ps0 += s[nt][0] + s[nt][1];
            ps1 += s[nt][2] + s[nt][3];
        }
        ps0 += __shfl_xor_sync(0xffffffffu, ps0, 1);
        ps0 += __shfl_xor_sync(0xffffffffu, ps0, 2);
        ps1 += __shfl_xor_sync(0xffffffffu, ps1, 1);
        ps1 += __shfl_xor_sync(0xffffffffu, ps1, 2);
        l0 = l0 * sc0 + ps0;
        l1 = l1 * sc1 + ps1;

        // ---- pack P (C-frag == A-frag layout), rescale O ----
        uint32_t aph[2][4], apl[2][4];
#pragma unroll
        for (int ks = 0; ks < 2; ks++) {
            packsplit(s[2 * ks][0], s[2 * ks][1], aph[ks][0], apl[ks][0]);
            packsplit(s[2 * ks][2], s[2 * ks][3], aph[ks][1], apl[ks][1]);
            packsplit(s[2 * ks + 1][0], s[2 * ks + 1][1], aph[ks][2], apl[ks][2]);
            packsplit(s[2 * ks + 1][2], s[2 * ks + 1][3], aph[ks][3], apl[ks][3]);
        }
#pragma unroll
        for (int nt = 0; nt < 8; nt++) {
            o[nt][0] *= sc0; o[nt][1] *= sc0;
            o[nt][2] *= sc1; o[nt][3] *= sc1;
        }

        // ---- O += P V ----
#pragma unroll
        for (int ks = 0; ks < 2; ks++) {
#pragma unroll
            for (int dp = 0; dp < 4; dp++) {
                uint32_t bh4[4], bl4[4];
                ldsm4t(sVh + vOff + ks * 2304 + dp * 32, bh4[0], bh4[1], bh4[2], bh4[3]);
                ldsm4t(sVl + vOff + ks * 2304 + dp * 32, bl4[0], bl4[1], bl4[2], bl4[3]);
                mma_bf(o[2 * dp], aph[ks], bh4[0], bh4[1]);
                mma_bf(o[2 * dp], aph[ks], bl4[0], bl4[1]);
                mma_bf(o[2 * dp], apl[ks], bh4[0], bh4[1]);
                mma_bf(o[2 * dp + 1], aph[ks], bh4[2], bh4[3]);
                mma_bf(o[2 * dp + 1], aph[ks], bl4[2], bl4[3]);
                mma_bf(o[2 * dp + 1], apl[ks], bh4[2], bh4[3]);
            }
        }

        __syncthreads();
        if (kt + 2 < 33) { A_ISSUE(kt + 2, kt & 1); }
        else cpa_commit();
    }

    // ---- finalize: ctx = O / l, split-bf16 write ----
    const float i0 = (l0 > 0.f) ? 1.f / l0 : 0.f;
    const float i1 = (l1 > 0.f) ? 1.f / l1 : 0.f;
#pragma unroll
    for (int nt = 0; nt < 8; nt++) {
        const int d0 = h * DH + nt * 8 + 2 * qd;
        uint32_t hi, lo;
        if (gq0 < NP_) {
            packsplit(o[nt][0] * i0, o[nt][1] * i0, hi, lo);
            const size_t off = (size_t)(b * NP_ + gq0) * EM + d0;
            *(uint32_t*)(g_ch + off) = hi; *(uint32_t*)(g_cl + off) = lo;
        }
        if (gq1 < NP_) {
            packsplit(o[nt][2] * i1, o[nt][3] * i1, hi, lo);
            const size_t off = (size_t)(b * NP_ + gq1) * EM + d0;
            *(uint32_t*)(g_ch + off) = hi; *(uint32_t*)(g_cl + off) = lo;
        }
    }
#undef A_ISSUE
}

// ---------------------------------------------------------------------------
extern "C" void kernel_launch(void* const* d_in, const int* in_sizes, int n_in,
                              void* d_out, int out_size)
{
    const float* x = (const float*)d_in[0];
    const float* abias = (const float*)d_in[1];
    const void* pmask = (const void*)d_in[2];
    const float* Ws[4] = {(const float*)d_in[3], (const float*)d_in[5],
                          (const float*)d_in[7], (const float*)d_in[9]};
    const float* bs[4] = {(const float*)d_in[4], (const float*)d_in[6],
                          (const float*)d_in[8], (const float*)d_in[10]};
    float* out = (float*)d_out;

    void *xh, *xl, *wh, *wl, *qh, *ql, *kh, *kl, *vh, *vl, *ch, *cl;
    cudaGetSymbolAddress(&xh, g_xh); cudaGetSymbolAddress(&xl, g_xl);
    cudaGetSymbolAddress(&wh, g_wh); cudaGetSymbolAddress(&wl, g_wl);
    cudaGetSymbolAddress(&qh, g_qh); cudaGetSymbolAddress(&ql, g_ql);
    cudaGetSymbolAddress(&kh, g_kh); cudaGetSymbolAddress(&kl, g_kl);
    cudaGetSymbolAddress(&vh, g_vh); cudaGetSymbolAddress(&vl, g_vl);
    cudaGetSymbolAddress(&ch, g_ch); cudaGetSymbolAddress(&cl, g_cl);

    cudaFuncSetAttribute(gemm_mma<1>, cudaFuncAttributeMaxDynamicSharedMemorySize, 2 * G_STG);
    cudaFuncSetAttribute(gemm_mma<0>, cudaFuncAttributeMaxDynamicSharedMemorySize, 2 * G_STG);
    cudaFuncSetAttribute(attn_mma, cudaFuncAttributeMaxDynamicSharedMemorySize,
                         A_QSZ + 2 * A_STG);

    mask_detect_kernel<<<1, 32>>>((const unsigned int*)pmask);
    mask_convert_kernel<<<1024, 256>>>(pmask);

    split_kernel<<<(XE / 4 + 255) / 256, 256>>>((const float4*)x,
        (uint32_t*)xh, (uint32_t*)xl, XE / 4);
    for (int i = 0; i < 4; i++)
        split_kernel<<<WE / 4 / 256, 256>>>((const float4*)Ws[i],
            (uint32_t*)((__nv_bfloat16*)wh + (size_t)i * WE),
            (uint32_t*)((__nv_bfloat16*)wl + (size_t)i * WE), WE / 4);

    dim3 gg(129, 8);
    gemm_mma<1><<<gg, 128, 2 * G_STG>>>((const __nv_bfloat16*)xh, (const __nv_bfloat16*)xl,
        (const __nv_bfloat16*)wh, (const __nv_bfloat16*)wl, bs[0],
        (__nv_bfloat16*)qh, (__nv_bfloat16*)ql, nullptr);
    gemm_mma<1><<<gg, 128, 2 * G_STG>>>((const __nv_bfloat16*)xh, (const __nv_bfloat16*)xl,
        (const __nv_bfloat16*)wh + (size_t)1 * WE, (const __nv_bfloat16*)wl + (size_t)1 * WE, bs[1],
        (__nv_bfloat16*)kh, (__nv_bfloat16*)kl, nullptr);
    gemm_mma<1><<<gg, 128, 2 * G_STG>>>((const __nv_bfloat16*)xh, (const __nv_bfloat16*)xl,
        (const __nv_bfloat16*)wh + (size_t)2 * WE, (const __nv_bfloat16*)wl + (size_t)2 * WE, bs[2],
        (__nv_bfloat16*)vh, (__nv_bfloat16*)vl, nullptr);

    attn_mma<<<dim3(17, 64), 128, A_QSZ + 2 * A_STG>>>(abias);

    gemm_mma<0><<<gg, 128, 2 * G_STG>>>((const __nv_bfloat16*)ch, (const __nv_bfloat16*)cl,
        (const __nv_bfloat16*)wh + (size_t)3 * WE, (const __nv_bfloat16*)wl + (size_t)3 * WE, bs[3],
        nullptr, nullptr, out);
}

// round 12
// speedup vs baseline: 4.0398x; 1.1611x over previous
#include <cuda_runtime.h>
#include <cuda_bf16.h>
#include <cuda_fp16.h>
#include <math.h>
#include <stdint.h>

#define NB 8
#define NH 8
#define NP_ 1025
#define NPAD 1024
#define DH 64
#define EM 512
#define MROWS (NB * NP_)      // 8200
#define XE (MROWS * EM)       // 4198400
#define WE (EM * EM)          // 262144
#define FB_COLS 1056

__device__ __align__(16) __nv_bfloat16 g_xh[XE], g_xl[XE];
__device__ __align__(16) __nv_bfloat16 g_wh[4][WE], g_wl[4][WE];
__device__ __align__(16) __nv_bfloat16 g_qh[XE], g_ql[XE];
__device__ __align__(16) __nv_bfloat16 g_kh[XE], g_kl[XE];
__device__ __align__(16) __nv_bfloat16 g_vh[XE], g_vl[XE];   // fp16 bits
__device__ __align__(16) __nv_bfloat16 g_ch[XE], g_cl[XE];
__device__ __align__(16) float g_fb[(size_t)NB * NH * NP_ * FB_COLS];
__device__ int g_mask_mode;

// ---------------- helpers ---------------------------------------------------
__device__ __forceinline__ uint32_t smem_u32(const void* p) {
    return (uint32_t)__cvta_generic_to_shared(p);
}
__device__ __forceinline__ void ldsm4(uint32_t a, uint32_t& r0, uint32_t& r1,
                                      uint32_t& r2, uint32_t& r3) {
    asm volatile("ldmatrix.sync.aligned.m8n8.x4.shared.b16 {%0,%1,%2,%3},[%4];"
                 : "=r"(r0), "=r"(r1), "=r"(r2), "=r"(r3) : "r"(a));
}
__device__ __forceinline__ void ldsm4t(uint32_t a, uint32_t& r0, uint32_t& r1,
                                       uint32_t& r2, uint32_t& r3) {
    asm volatile("ldmatrix.sync.aligned.m8n8.x4.trans.shared.b16 {%0,%1,%2,%3},[%4];"
                 : "=r"(r0), "=r"(r1), "=r"(r2), "=r"(r3) : "r"(a));
}
__device__ __forceinline__ void mma_bf(float* c, const uint32_t* a, uint32_t b0, uint32_t b1) {
    asm volatile(
        "mma.sync.aligned.m16n8k16.row.col.f32.bf16.bf16.f32 "
        "{%0,%1,%2,%3},{%4,%5,%6,%7},{%8,%9},{%0,%1,%2,%3};"
        : "+f"(c[0]), "+f"(c[1]), "+f"(c[2]), "+f"(c[3])
        : "r"(a[0]), "r"(a[1]), "r"(a[2]), "r"(a[3]), "r"(b0), "r"(b1));
}
__device__ __forceinline__ void mma_f16(float* c, const uint32_t* a, uint32_t b0, uint32_t b1) {
    asm volatile(
        "mma.sync.aligned.m16n8k16.row.col.f32.f16.f16.f32 "
        "{%0,%1,%2,%3},{%4,%5,%6,%7},{%8,%9},{%0,%1,%2,%3};"
        : "+f"(c[0]), "+f"(c[1]), "+f"(c[2]), "+f"(c[3])
        : "r"(a[0]), "r"(a[1]), "r"(a[2]), "r"(a[3]), "r"(b0), "r"(b1));
}
__device__ __forceinline__ void packsplit(float a, float b, uint32_t& hi, uint32_t& lo) {
    __nv_bfloat16 ha = __float2bfloat16(a), hb = __float2bfloat16(b);
    __nv_bfloat16 la = __float2bfloat16(a - __bfloat162float(ha));
    __nv_bfloat16 lb = __float2bfloat16(b - __bfloat162float(hb));
    __nv_bfloat162 H = __halves2bfloat162(ha, hb), L = __halves2bfloat162(la, lb);
    hi = *(uint32_t*)&H; lo = *(uint32_t*)&L;
}
__device__ __forceinline__ void packsplit16(float a, float b, uint32_t& hi, uint32_t& lo) {
    __half ha = __float2half_rn(a), hb = __float2half_rn(b);
    __half la = __float2half_rn(a - __half2float(ha));
    __half lb = __float2half_rn(b - __half2float(hb));
    __half2 H = __halves2half2(ha, hb), L = __halves2half2(la, lb);
    hi = *(uint32_t*)&H; lo = *(uint32_t*)&L;
}
__device__ __forceinline__ uint32_t pack_f16x2(float lo, float hi) {
    uint32_t r;
    asm("cvt.rn.f16x2.f32 %0,%1,%2;" : "=r"(r) : "f"(hi), "f"(lo));
    return r;
}
__device__ __forceinline__ float fexp2(float x) {
    float r;
    asm("ex2.approx.ftz.f32 %0,%1;" : "=f"(r) : "f"(x));
    return r;
}
__device__ __forceinline__ void cpa16(uint32_t dst, const void* src, int sz) {
    asm volatile("cp.async.cg.shared.global [%0], [%1], 16, %2;"
                 :: "r"(dst), "l"(src), "r"(sz));
}
__device__ __forceinline__ void cpa16f(uint32_t dst, const void* src) {
    asm volatile("cp.async.cg.shared.global [%0], [%1], 16;"
                 :: "r"(dst), "l"(src));
}
__device__ __forceinline__ void cpa_commit() {
    asm volatile("cp.async.commit_group;");
}
template <int N> __device__ __forceinline__ void cpa_wait() {
    asm volatile("cp.async.wait_group %0;" :: "n"(N));
}

// ---------------- mask dtype detect -----------------------------------------
__global__ void mask_detect_kernel(const unsigned int* __restrict__ pm) {
    int t = threadIdx.x;
    bool aF = true, aI = true;
    for (int i = t; i < 4096; i += 32) {
        unsigned int w = pm[i];
        if (!(w == 0u || w == 0x3F800000u)) aF = false;
        if (w > 1u) aI = false;
    }
    aF = __all_sync(0xffffffffu, aF);
    aI = __all_sync(0xffffffffu, aI);
    if (t == 0) g_mask_mode = aF ? 0 : (aI ? 1 : 2);
}

// ---------------- fused bias+mask (in log2 domain) ---------------------------
// g_fb[bh][q][c] = allowed ? abias[bh][q][c]*log2e : -1e30 ; cols >= NP_ -> -1e30
__global__ __launch_bounds__(256) void fuse_kernel(const float* __restrict__ abias,
                                                   const void* __restrict__ pm) {
    const size_t total = (size_t)NB * NH * NP_ * (FB_COLS / 4);
    size_t idx = (size_t)blockIdx.x * 256 + threadIdx.x;
    if (idx >= total) return;
    const int c4 = (int)(idx % (FB_COLS / 4));
    const size_t rq = idx / (FB_COLS / 4);
    const int q = (int)(rq % NP_);
    const int bh = (int)(rq / NP_);
    const int b = bh >> 3;
    const int mode = g_mask_mode;
    const float* arow = abias + rq * NP_;
    float4 out;
    float* o = &out.x;
#pragma unroll
    for (int j = 0; j < 4; j++) {
        const int c = c4 * 4 + j;
        float v = -1e30f;
        if (c < NP_) {
            bool ok = (q == 0) || (c == 0);
            if (!ok) {
                const size_t mi = ((size_t)b * NPAD + (q - 1)) * NPAD + (c - 1);
                if (mode == 0)      ok = ((const float*)pm)[mi] != 0.f;
                else if (mode == 1) ok = ((const int*)pm)[mi] != 0;
                else                ok = ((const unsigned char*)pm)[mi] != 0;
            }
            if (ok) v = arow[c] * 1.44269504f;
        }
        o[j] = v;
    }
    *(float4*)(g_fb + rq * FB_COLS + c4 * 4) = out;
}

// ---------------- fp32 -> bf16 hi/lo split ----------------------------------
__global__ __launch_bounds__(256) void split_kernel(const float4* __restrict__ src,
                                                    uint32_t* __restrict__ h,
                                                    uint32_t* __restrict__ l,
                                                    int n4) {
    int i = blockIdx.x * 256 + threadIdx.x;
    if (i >= n4) return;
    float4 v = src[i];
    uint32_t h0, l0, h1, l1;
    packsplit(v.x, v.y, h0, l0);
    packsplit(v.z, v.w, h1, l1);
    h[2 * i] = h0; h[2 * i + 1] = h1;
    l[2 * i] = l0; l[2 * i + 1] = l1;
}

// ---------------- GEMM: C = A @ W^T + b  (split-bf16, cp.async 2-stage) ------
// SPLIT: 0 = fp32 out, 1 = bf16 hi/lo out, 2 = fp16 hi/lo out
#define G_STG 36864
template <int SPLIT>
__global__ __launch_bounds__(128) void gemm_mma(
    const __nv_bfloat16* __restrict__ Agh, const __nv_bfloat16* __restrict__ Agl,
    const __nv_bfloat16* __restrict__ Wh, const __nv_bfloat16* __restrict__ Wl,
    const float* __restrict__ bias,
    __nv_bfloat16* __restrict__ Oh, __nv_bfloat16* __restrict__ Ol,
    float* __restrict__ Of)
{
    extern __shared__ __align__(16) char dsm[];
    const uint32_t dbase = smem_u32(dsm);
    const int m0 = blockIdx.x * 64, n0 = blockIdx.y * 64;
    const int t = threadIdx.x, warp = t >> 5, lane = t & 31;
    const int g = lane >> 2, qd = lane & 3;

    float c[8][4];
#pragma unroll
    for (int i = 0; i < 8; i++)
#pragma unroll
        for (int j = 0; j < 4; j++) c[i][j] = 0.f;

    const int lrow = t >> 1, lcb = (t & 1) << 5;
    const int gmr = m0 + lrow;
    const bool mv = gmr < MROWS;
    const size_t aB = (size_t)(mv ? gmr : 0) * EM + lcb;
    const size_t bB = (size_t)(n0 + lrow) * EM + lcb;
    const uint32_t offA = (uint32_t)((lrow * 72 + lcb) * 2);
    const int asz = mv ? 16 : 0;
    const uint32_t aOff = (uint32_t)(((warp * 16 + (lane & 15)) * 72 + ((lane >> 4) << 3)) * 2);
    const uint32_t bOff = (uint32_t)((((lane & 7) + ((lane >> 4) << 3)) * 72 +
                                      (((lane >> 3) & 1) << 3)) * 2);

#define G_ISSUE(k0, s) do {                                                     \
        const uint32_t sb_ = dbase + (s) * G_STG;                               \
        _Pragma("unroll")                                                       \
        for (int i_ = 0; i_ < 4; i_++) {                                        \
            cpa16(sb_ + offA + i_ * 16,          Agh + aB + (k0) + i_ * 8, asz);\
            cpa16(sb_ + 9216 + offA + i_ * 16,   Agl + aB + (k0) + i_ * 8, asz);\
            cpa16(sb_ + 18432 + offA + i_ * 16,  Wh + bB + (k0) + i_ * 8, 16);  \
            cpa16(sb_ + 27648 + offA + i_ * 16,  Wl + bB + (k0) + i_ * 8, 16);  \
        }                                                                       \
        cpa_commit();                                                           \
    } while (0)

    G_ISSUE(0, 0);
    G_ISSUE(64, 1);

    for (int ki = 0; ki < 8; ki++) {
        cpa_wait<1>();
        __syncthreads();
        const uint32_t sb = dbase + (ki & 1) * G_STG;
        const uint32_t sAh = sb, sAl = sb + 9216, sBh = sb + 18432, sBl = sb + 27648;
#pragma unroll
        for (int ks = 0; ks < 4; ks++) {
            uint32_t ah[4], al[4];
            ldsm4(sAh + aOff + ks * 32, ah[0], ah[1], ah[2], ah[3]);
            ldsm4(sAl + aOff + ks * 32, al[0], al[1], al[2], al[3]);
#pragma unroll
            for (int np = 0; np < 4; np++) {
                uint32_t bh4[4], bl4[4];
                ldsm4(sBh + bOff + np * 2304 + ks * 32, bh4[0], bh4[1], bh4[2], bh4[3]);
                ldsm4(sBl + bOff + np * 2304 + ks * 32, bl4[0], bl4[1], bl4[2], bl4[3]);
                mma_bf(c[2 * np], ah, bh4[0], bh4[1]);
                mma_bf(c[2 * np], ah, bl4[0], bl4[1]);
                mma_bf(c[2 * np], al, bh4[0], bh4[1]);
                mma_bf(c[2 * np + 1], ah, bh4[2], bh4[3]);
                mma_bf(c[2 * np + 1], ah, bl4[2], bl4[3]);
                mma_bf(c[2 * np + 1], al, bh4[2], bh4[3]);
            }
        }
        __syncthreads();
        if (ki + 2 < 8) { G_ISSUE((ki + 2) * 64, ki & 1); }
        else cpa_commit();
    }

    const int r0g = m0 + warp * 16 + g, r1g = r0g + 8;
#pragma unroll
    for (int nt = 0; nt < 8; nt++) {
        const int cn = n0 + nt * 8 + 2 * qd;
        const float bx = __ldg(bias + cn), by = __ldg(bias + cn + 1);
        if (SPLIT == 1) {
            uint32_t hi, lo;
            if (r0g < MROWS) {
                packsplit(c[nt][0] + bx, c[nt][1] + by, hi, lo);
                *(uint32_t*)(Oh + (size_t)r0g * EM + cn) = hi;
                *(uint32_t*)(Ol + (size_t)r0g * EM + cn) = lo;
            }
            if (r1g < MROWS) {
                packsplit(c[nt][2] + bx, c[nt][3] + by, hi, lo);
                *(uint32_t*)(Oh + (size_t)r1g * EM + cn) = hi;
                *(uint32_t*)(Ol + (size_t)r1g * EM + cn) = lo;
            }
        } else if (SPLIT == 2) {
            uint32_t hi, lo;
            if (r0g < MROWS) {
                packsplit16(c[nt][0] + bx, c[nt][1] + by, hi, lo);
                *(uint32_t*)(Oh + (size_t)r0g * EM + cn) = hi;
                *(uint32_t*)(Ol + (size_t)r0g * EM + cn) = lo;
            }
            if (r1g < MROWS) {
                packsplit16(c[nt][2] + bx, c[nt][3] + by, hi, lo);
                *(uint32_t*)(Oh + (size_t)r1g * EM + cn) = hi;
                *(uint32_t*)(Ol + (size_t)r1g * EM + cn) = lo;
            }
        } else {
            if (r0g < MROWS)
                *(float2*)(Of + (size_t)r0g * EM + cn) = make_float2(c[nt][0] + bx, c[nt][1] + by);
            if (r1g < MROWS)
                *(float2*)(Of + (size_t)r1g * EM + cn) = make_float2(c[nt][2] + bx, c[nt][3] + by);
        }
    }
#undef G_ISSUE
}

// ---------------- flash attention -------------------------------------------
// stage: Kh 0, Kl 4608, Vh 9216, Vl 13824 (fp16), bias 18432 (64x36 f32 = 9216)
#define A_STG 27648
__global__ __launch_bounds__(128) void attn_mma() {
    extern __shared__ __align__(16) char dsm[];
    const uint32_t dbase = smem_u32(dsm);

    const int bh = blockIdx.y;
    const int b = bh >> 3, h = bh & 7;
    const int q0 = blockIdx.x * 64;
    const int t = threadIdx.x, warp = t >> 5, lane = t & 31;
    const int g = lane >> 2, qd = lane & 3;
    const uint4 z4 = make_uint4(0, 0, 0, 0);

    // ---- phase 0: load Q tile to smem, hoist fragments, then free smem ----
    {
        const int row = t >> 1, cb = (t & 1) << 5;
        const int gq = q0 + row;
        const bool v = gq < NP_;
        const size_t base = (size_t)(b * NP_ + (v ? gq : 0)) * EM + h * DH + cb;
#pragma unroll
        for (int i = 0; i < 4; i++) {
            *(uint4*)(dsm + (row * 72 + cb + i * 8) * 2) =
                v ? *(const uint4*)(g_qh + base + i * 8) : z4;
            *(uint4*)(dsm + 9216 + (row * 72 + cb + i * 8) * 2) =
                v ? *(const uint4*)(g_ql + base + i * 8) : z4;
        }
    }
    __syncthreads();
    const uint32_t qOff = (uint32_t)(((warp * 16 + (lane & 15)) * 72 + ((lane >> 4) << 3)) * 2);
    uint32_t qhf[4][4], qlf[4][4];
#pragma unroll
    for (int ks = 0; ks < 4; ks++) {
        ldsm4(dbase + qOff + ks * 32, qhf[ks][0], qhf[ks][1], qhf[ks][2], qhf[ks][3]);
        ldsm4(dbase + 9216 + qOff + ks * 32, qlf[ks][0], qlf[ks][1], qlf[ks][2], qlf[ks][3]);
    }
    __syncthreads();   // all warps done reading Q before pipeline overwrites

    // ---- pipeline mappings ----
    const int kvrow = t >> 2, kvcb = (t & 3) << 4;
    const uint32_t offKV = (uint32_t)((kvrow * 72 + kvcb) * 2);
    const int fbrow_i = t >> 1;
    const float* fbrow = g_fb + ((size_t)bh * NP_ + min(q0 + fbrow_i, NP_ - 1)) * FB_COLS;
    const uint32_t offFB = (uint32_t)(18432 + fbrow_i * 144 + (t & 1) * 64);

#define A_ISSUE(kt, s) do {                                                        \
        const int gk_ = (kt) * 32 + kvrow;                                         \
        const bool v_ = gk_ < NP_;                                                 \
        const size_t gb_ = (size_t)(b * NP_ + (v_ ? gk_ : 0)) * EM + h * DH + kvcb;\
        const int sz_ = v_ ? 16 : 0;                                               \
        const uint32_t sb_ = dbase + (s) * A_STG;                                  \
        _Pragma("unroll")                                                          \
        for (int i_ = 0; i_ < 2; i_++) {                                           \
            cpa16(sb_ + offKV + i_ * 16,          g_kh + gb_ + i_ * 8, sz_);       \
            cpa16(sb_ + 4608 + offKV + i_ * 16,   g_kl + gb_ + i_ * 8, sz_);       \
            cpa16(sb_ + 9216 + offKV + i_ * 16,   g_vh + gb_ + i_ * 8, sz_);       \
            cpa16(sb_ + 13824 + offKV + i_ * 16,  g_vl + gb_ + i_ * 8, sz_);       \
        }                                                                          \
        const float* fsrc_ = fbrow + (kt) * 32 + (t & 1) * 16;                     \
        _Pragma("unroll")                                                          \
        for (int j_ = 0; j_ < 4; j_++)                                             \
            cpa16f(sb_ + offFB + j_ * 16, fsrc_ + j_ * 4);                         \
        cpa_commit();                                                              \
    } while (0)

    A_ISSUE(0, 0);
    A_ISSUE(1, 1);

    const uint32_t kOff = (uint32_t)((((lane & 7) + ((lane >> 4) << 3)) * 72 +
                                      (((lane >> 3) & 1) << 3)) * 2);
    const uint32_t vOff = (uint32_t)((((lane & 7) + (((lane >> 3) & 1) << 3)) * 72 +
                                      ((lane >> 4) << 3)) * 2);
    const int gq0 = q0 + warp * 16 + g, gq1 = gq0 + 8;
    const int r0b = (warp * 16 + g) * 36, r1b = r0b + 8 * 36;

    float m0 = -1e30f, m1 = -1e30f, l0 = 0.f, l1 = 0.f;
    float o[8][4];
#pragma unroll
    for (int i = 0; i < 8; i++)
#pragma unroll
        for (int j = 0; j < 4; j++) o[i][j] = 0.f;

    const float SSC = 0.125f * 1.44269504f;

    for (int kt = 0; kt < 33; kt++) {
        cpa_wait<1>();
        __syncthreads();
        const uint32_t sb = dbase + (kt & 1) * A_STG;
        const uint32_t sKh = sb, sKl = sb + 4608, sVh = sb + 9216, sVl = sb + 13824;
        const float* sbias = (const float*)(dsm + (kt & 1) * A_STG + 18432);

        // ---- S = Q K^T (bf16 3-term) ----
        float s[4][4];
#pragma unroll
        for (int i = 0; i < 4; i++)
#pragma unroll
            for (int j = 0; j < 4; j++) s[i][j] = 0.f;
#pragma unroll
        for (int ks = 0; ks < 4; ks++) {
#pragma unroll
            for (int np = 0; np < 2; np++) {
                uint32_t bh4[4], bl4[4];
                ldsm4(sKh + kOff + np * 2304 + ks * 32, bh4[0], bh4[1], bh4[2], bh4[3]);
                ldsm4(sKl + kOff + np * 2304 + ks * 32, bl4[0], bl4[1], bl4[2], bl4[3]);
                mma_bf(s[2 * np], qhf[ks], bh4[0], bh4[1]);
                mma_bf(s[2 * np], qhf[ks], bl4[0], bl4[1]);
                mma_bf(s[2 * np], qlf[ks], bh4[0], bh4[1]);
                mma_bf(s[2 * np + 1], qhf[ks], bh4[2], bh4[3]);
                mma_bf(s[2 * np + 1], qhf[ks], bl4[2], bl4[3]);
                mma_bf(s[2 * np + 1], qlf[ks], bh4[2], bh4[3]);
            }
        }

        // ---- fused scale+bias+mask (log2 domain, from smem) ----
#pragma unroll
        for (int nt = 0; nt < 4; nt++) {
            const int cn = nt * 8 + 2 * qd;
            const float2 b0 = *(const float2*)(sbias + r0b + cn);
            const float2 b1 = *(const float2*)(sbias + r1b + cn);
            s[nt][0] = fmaf(s[nt][0], SSC, b0.x);
            s[nt][1] = fmaf(s[nt][1], SSC, b0.y);
            s[nt][2] = fmaf(s[nt][2], SSC, b1.x);
            s[nt][3] = fmaf(s[nt][3], SSC, b1.y);
        }

        // ---- online softmax (base 2) ----
        float lm0 = -1e30f, lm1 = -1e30f;
#pragma unroll
        for (int nt = 0; nt < 4; nt++) {
            lm0 = fmaxf(lm0, fmaxf(s[nt][0], s[nt][1]));
            lm1 = fmaxf(lm1, fmaxf(s[nt][2], s[nt][3]));
        }
        lm0 = fmaxf(lm0, __shfl_xor_sync(0xffffffffu, lm0, 1));
        lm0 = fmaxf(lm0, __shfl_xor_sync(0xffffffffu, lm0, 2));
        lm1 = fmaxf(lm1, __shfl_xor_sync(0xffffffffu, lm1, 1));
        lm1 = fmaxf(lm1, __shfl_xor_sync(0xffffffffu, lm1, 2));
        const float mn0 = fmaxf(m0, lm0), mn1 = fmaxf(m1, lm1);
        const float sc0 = fexp2(m0 - mn0), sc1 = fexp2(m1 - mn1);
        m0 = mn0; m1 = mn1;

        float ps0 = 0.f, ps1 = 0.f;
#pragma unroll
        for (int nt = 0; nt < 4; nt++) {
            s[nt][0] = fexp2(s[nt][0] - mn0);
            s[nt][1] = fexp2(s[nt][1] - mn0);
            s[nt][2] = fexp2(s[nt][2] - mn1);
            s[nt][3] = fexp2(s[nt][3] - mn1);
            ps0 += s[nt][0] + s[nt][1];
            ps1 += s[nt][2] + s[nt][3];
        }
        ps0 += __shfl_xor_sync(0xffffffffu, ps0, 1);
        ps0 += __shfl_xor_sync(0xffffffffu, ps0, 2);
        ps1 += __shfl_xor_sync(0xffffffffu, ps1, 1);
        ps1 += __shfl_xor_sync(0xffffffffu, ps1, 2);
        l0 = l0 * sc0 + ps0;
        l1 = l1 * sc1 + ps1;

        // ---- P -> fp16 A-frags, rescale O ----
        uint32_t ap[2][4];
#pragma unroll
        for (int ks = 0; ks < 2; ks++) {
            ap[ks][0] = pack_f16x2(s[2 * ks][0], s[2 * ks][1]);
            ap[ks][1] = pack_f16x2(s[2 * ks][2], s[2 * ks][3]);
            ap[ks][2] = pack_f16x2(s[2 * ks + 1][0], s[2 * ks + 1][1]);
            ap[ks][3] = pack_f16x2(s[2 * ks + 1][2], s[2 * ks + 1][3]);
        }
#pragma unroll
        for (int nt = 0; nt < 8; nt++) {
            o[nt][0] *= sc0; o[nt][1] *= sc0;
            o[nt][2] *= sc1; o[nt][3] *= sc1;
        }

        // ---- O += P V (fp16, V hi+lo) ----
#pragma unroll
        for (int ks = 0; ks < 2; ks++) {
#pragma unroll
            for (int dp = 0; dp < 4; dp++) {
                uint32_t vh4[4], vl4[4];
                ldsm4t(sVh + vOff + ks * 2304 + dp * 32, vh4[0], vh4[1], vh4[2], vh4[3]);
                ldsm4t(sVl + vOff + ks * 2304 + dp * 32, vl4[0], vl4[1], vl4[2], vl4[3]);
                mma_f16(o[2 * dp], ap[ks], vh4[0], vh4[1]);
                mma_f16(o[2 * dp], ap[ks], vl4[0], vl4[1]);
                mma_f16(o[2 * dp + 1], ap[ks], vh4[2], vh4[3]);
                mma_f16(o[2 * dp + 1], ap[ks], vl4[2], vl4[3]);
            }
        }

        __syncthreads();
        if (kt + 2 < 33) { A_ISSUE(kt + 2, kt & 1); }
        else cpa_commit();
    }

    // ---- finalize: ctx = O / l, split-bf16 write ----
    const float i0 = (l0 > 0.f) ? 1.f / l0 : 0.f;
    const float i1 = (l1 > 0.f) ? 1.f / l1 : 0.f;
#pragma unroll
    for (int nt = 0; nt < 8; nt++) {
        const int d0 = h * DH + nt * 8 + 2 * qd;
        uint32_t hi, lo;
        if (gq0 < NP_) {
            packsplit(o[nt][0] * i0, o[nt][1] * i0, hi, lo);
            const size_t off = (size_t)(b * NP_ + gq0) * EM + d0;
            *(uint32_t*)(g_ch + off) = hi; *(uint32_t*)(g_cl + off) = lo;
        }
        if (gq1 < NP_) {
            packsplit(o[nt][2] * i1, o[nt][3] * i1, hi, lo);
            const size_t off = (size_t)(b * NP_ + gq1) * EM + d0;
            *(uint32_t*)(g_ch + off) = hi; *(uint32_t*)(g_cl + off) = lo;
        }
    }
#undef A_ISSUE
}

// ---------------------------------------------------------------------------
extern "C" void kernel_launch(void* const* d_in, const int* in_sizes, int n_in,
                              void* d_out, int out_size)
{
    const float* x = (const float*)d_in[0];
    const float* abias = (const float*)d_in[1];
    const void* pmask = (const void*)d_in[2];
    const float* Ws[4] = {(const float*)d_in[3], (const float*)d_in[5],
                          (const float*)d_in[7], (const float*)d_in[9]};
    const float* bs[4] = {(const float*)d_in[4], (const float*)d_in[6],
                          (const float*)d_in[8], (const float*)d_in[10]};
    float* out = (float*)d_out;

    void *xh, *xl, *wh, *wl, *qh, *ql, *kh, *kl, *vh, *vl, *ch, *cl;
    cudaGetSymbolAddress(&xh, g_xh); cudaGetSymbolAddress(&xl, g_xl);
    cudaGetSymbolAddress(&wh, g_wh); cudaGetSymbolAddress(&wl, g_wl);
    cudaGetSymbolAddress(&qh, g_qh); cudaGetSymbolAddress(&ql, g_ql);
    cudaGetSymbolAddress(&kh, g_kh); cudaGetSymbolAddress(&kl, g_kl);
    cudaGetSymbolAddress(&vh, g_vh); cudaGetSymbolAddress(&vl, g_vl);
    cudaGetSymbolAddress(&ch, g_ch); cudaGetSymbolAddress(&cl, g_cl);

    cudaFuncSetAttribute(gemm_mma<1>, cudaFuncAttributeMaxDynamicSharedMemorySize, 2 * G_STG);
    cudaFuncSetAttribute(gemm_mma<2>, cudaFuncAttributeMaxDynamicSharedMemorySize, 2 * G_STG);
    cudaFuncSetAttribute(gemm_mma<0>, cudaFuncAttributeMaxDynamicSharedMemorySize, 2 * G_STG);
    cudaFuncSetAttribute(attn_mma, cudaFuncAttributeMaxDynamicSharedMemorySize, 2 * A_STG);

    mask_detect_kernel<<<1, 32>>>((const unsigned int*)pmask);

    {
        const size_t total = (size_t)NB * NH * NP_ * (FB_COLS / 4);
        fuse_kernel<<<(unsigned)((total + 255) / 256), 256>>>(abias, pmask);
    }

    split_kernel<<<(XE / 4 + 255) / 256, 256>>>((const float4*)x,
        (uint32_t*)xh, (uint32_t*)xl, XE / 4);
    for (int i = 0; i < 4; i++)
        split_kernel<<<WE / 4 / 256, 256>>>((const float4*)Ws[i],
            (uint32_t*)((__nv_bfloat16*)wh + (size_t)i * WE),
            (uint32_t*)((__nv_bfloat16*)wl + (size_t)i * WE), WE / 4);

    dim3 gg(129, 8);
    gemm_mma<1><<<gg, 128, 2 * G_STG>>>((const __nv_bfloat16*)xh, (const __nv_bfloat16*)xl,
        (const __nv_bfloat16*)wh, (const __nv_bfloat16*)wl, bs[0],
        (__nv_bfloat16*)qh, (__nv_bfloat16*)ql, nullptr);
    gemm_mma<1><<<gg, 128, 2 * G_STG>>>((const __nv_bfloat16*)xh, (const __nv_bfloat16*)xl,
        (const __nv_bfloat16*)wh + (size_t)1 * WE, (const __nv_bfloat16*)wl + (size_t)1 * WE, bs[1],
        (__nv_bfloat16*)kh, (__nv_bfloat16*)kl, nullptr);
    gemm_mma<2><<<gg, 128, 2 * G_STG>>>((const __nv_bfloat16*)xh, (const __nv_bfloat16*)xl,
        (const __nv_bfloat16*)wh + (size_t)2 * WE, (const __nv_bfloat16*)wl + (size_t)2 * WE, bs[2],
        (__nv_bfloat16*)vh, (__nv_bfloat16*)vl, nullptr);

    attn_mma<<<dim3(17, 64), 128, 2 * A_STG>>>();

    gemm_mma<0><<<gg, 128, 2 * G_STG>>>((const __nv_bfloat16*)ch, (const __nv_bfloat16*)cl,
        (const __nv_bfloat16*)wh + (size_t)3 * WE, (const __nv_bfloat16*)wl + (size_t)3 * WE, bs[3],
        nullptr, nullptr, out);
}

// round 15
// speedup vs baseline: 5.1343x; 1.2709x over previous
#include <cuda_runtime.h>
#include <cuda_bf16.h>
#include <cuda_fp16.h>
#include <math.h>
#include <stdint.h>

#define NB 8
#define NH 8
#define NP_ 1025
#define NPAD 1024
#define DH 64
#define EM 512
#define MROWS (NB * NP_)
#define XE (MROWS * EM)
#define WE (EM * EM)
#define FB_COLS 1056

__device__ __align__(16) __nv_bfloat16 g_xh[XE], g_xl[XE];
__device__ __align__(16) __nv_bfloat16 g_wh[4][WE], g_wl[4][WE];
__device__ __align__(16) __half g_xf[XE], g_wqf[WE], g_wkf[WE];
__device__ __align__(16) __half g_qf[XE], g_kf[XE];
__device__ __align__(16) __nv_bfloat16 g_vh[XE], g_vl[XE];   // fp16 bits
__device__ __align__(16) __nv_bfloat16 g_ch[XE], g_cl[XE];
__device__ __align__(16) __half g_fb[(size_t)NB * NH * NP_ * FB_COLS];
__device__ int g_mask_mode;

// ---------------- helpers ---------------------------------------------------
__device__ __forceinline__ uint32_t smem_u32(const void* p) {
    return (uint32_t)__cvta_generic_to_shared(p);
}
__device__ __forceinline__ void ldsm4(uint32_t a, uint32_t& r0, uint32_t& r1,
                                      uint32_t& r2, uint32_t& r3) {
    asm volatile("ldmatrix.sync.aligned.m8n8.x4.shared.b16 {%0,%1,%2,%3},[%4];"
                 : "=r"(r0), "=r"(r1), "=r"(r2), "=r"(r3) : "r"(a));
}
__device__ __forceinline__ void ldsm4t(uint32_t a, uint32_t& r0, uint32_t& r1,
                                       uint32_t& r2, uint32_t& r3) {
    asm volatile("ldmatrix.sync.aligned.m8n8.x4.trans.shared.b16 {%0,%1,%2,%3},[%4];"
                 : "=r"(r0), "=r"(r1), "=r"(r2), "=r"(r3) : "r"(a));
}
__device__ __forceinline__ void mma_bf(float* c, const uint32_t* a, uint32_t b0, uint32_t b1) {
    asm volatile(
        "mma.sync.aligned.m16n8k16.row.col.f32.bf16.bf16.f32 "
        "{%0,%1,%2,%3},{%4,%5,%6,%7},{%8,%9},{%0,%1,%2,%3};"
        : "+f"(c[0]), "+f"(c[1]), "+f"(c[2]), "+f"(c[3])
        : "r"(a[0]), "r"(a[1]), "r"(a[2]), "r"(a[3]), "r"(b0), "r"(b1));
}
__device__ __forceinline__ void mma_f16(float* c, const uint32_t* a, uint32_t b0, uint32_t b1) {
    asm volatile(
        "mma.sync.aligned.m16n8k16.row.col.f32.f16.f16.f32 "
        "{%0,%1,%2,%3},{%4,%5,%6,%7},{%8,%9},{%0,%1,%2,%3};"
        : "+f"(c[0]), "+f"(c[1]), "+f"(c[2]), "+f"(c[3])
        : "r"(a[0]), "r"(a[1]), "r"(a[2]), "r"(a[3]), "r"(b0), "r"(b1));
}
__device__ __forceinline__ void packsplit(float a, float b, uint32_t& hi, uint32_t& lo) {
    __nv_bfloat16 ha = __float2bfloat16(a), hb = __float2bfloat16(b);
    __nv_bfloat16 la = __float2bfloat16(a - __bfloat162float(ha));
    __nv_bfloat16 lb = __float2bfloat16(b - __bfloat162float(hb));
    __nv_bfloat162 H = __halves2bfloat162(ha, hb), L = __halves2bfloat162(la, lb);
    hi = *(uint32_t*)&H; lo = *(uint32_t*)&L;
}
__device__ __forceinline__ void packsplit16(float a, float b, uint32_t& hi, uint32_t& lo) {
    __half ha = __float2half_rn(a), hb = __float2half_rn(b);
    __half la = __float2half_rn(a - __half2float(ha));
    __half lb = __float2half_rn(b - __half2float(hb));
    __half2 H = __halves2half2(ha, hb), L = __halves2half2(la, lb);
    hi = *(uint32_t*)&H; lo = *(uint32_t*)&L;
}
__device__ __forceinline__ uint32_t pack_f16x2(float lo, float hi) {
    uint32_t r;
    asm("cvt.rn.f16x2.f32 %0,%1,%2;" : "=r"(r) : "f"(hi), "f"(lo));
    return r;
}
__device__ __forceinline__ float fexp2(float x) {
    float r;
    asm("ex2.approx.ftz.f32 %0,%1;" : "=f"(r) : "f"(x));
    return r;
}
__device__ __forceinline__ void cpa16(uint32_t dst, const void* src, int sz) {
    asm volatile("cp.async.cg.shared.global [%0], [%1], 16, %2;"
                 :: "r"(dst), "l"(src), "r"(sz));
}
__device__ __forceinline__ void cpa16f(uint32_t dst, const void* src) {
    asm volatile("cp.async.cg.shared.global [%0], [%1], 16;"
                 :: "r"(dst), "l"(src));
}
__device__ __forceinline__ void cpa_commit() {
    asm volatile("cp.async.commit_group;");
}
template <int N> __device__ __forceinline__ void cpa_wait() {
    asm volatile("cp.async.wait_group %0;" :: "n"(N));
}

// ---------------- mask dtype detect -----------------------------------------
__global__ void mask_detect_kernel(const unsigned int* __restrict__ pm) {
    int t = threadIdx.x;
    bool aF = true, aI = true;
    for (int i = t; i < 4096; i += 32) {
        unsigned int w = pm[i];
        if (!(w == 0u || w == 0x3F800000u)) aF = false;
        if (w > 1u) aI = false;
    }
    aF = __all_sync(0xffffffffu, aF);
    aI = __all_sync(0xffffffffu, aI);
    if (t == 0) g_mask_mode = aF ? 0 : (aI ? 1 : 2);
}

// ---------------- fused bias+mask in fp16 (log2 domain) ----------------------
__global__ __launch_bounds__(256) void fuse_kernel(const float* __restrict__ abias,
                                                   const void* __restrict__ pm) {
    const size_t total = (size_t)NB * NH * NP_ * (FB_COLS / 8);
    size_t idx = (size_t)blockIdx.x * 256 + threadIdx.x;
    if (idx >= total) return;
    const int c8 = (int)(idx % (FB_COLS / 8));
    const size_t rq = idx / (FB_COLS / 8);
    const int q = (int)(rq % NP_);
    const int bh = (int)(rq / NP_);
    const int b = bh >> 3;
    const int mode = g_mask_mode;
    const float* arow = abias + rq * NP_;
    __half out[8];
#pragma unroll
    for (int j = 0; j < 8; j++) {
        const int c = c8 * 8 + j;
        float v = -60000.f;
        if (c < NP_) {
            bool ok = (q == 0) || (c == 0);
            if (!ok) {
                const size_t mi = ((size_t)b * NPAD + (q - 1)) * NPAD + (c - 1);
                if (mode == 0)      ok = ((const float*)pm)[mi] != 0.f;
                else if (mode == 1) ok = ((const int*)pm)[mi] != 0;
                else                ok = ((const unsigned char*)pm)[mi] != 0;
            }
            if (ok) v = arow[c] * 1.44269504f;
        }
        out[j] = __float2half_rn(v);
    }
    *(uint4*)(g_fb + rq * FB_COLS + c8 * 8) = *(uint4*)out;
}

// ---------------- fp32 -> bf16 hi/lo split ----------------------------------
__global__ __launch_bounds__(256) void split_kernel(const float4* __restrict__ src,
                                                    uint32_t* __restrict__ h,
                                                    uint32_t* __restrict__ l,
                                                    int n4) {
    int i = blockIdx.x * 256 + threadIdx.x;
    if (i >= n4) return;
    float4 v = src[i];
    uint32_t h0, l0, h1, l1;
    packsplit(v.x, v.y, h0, l0);
    packsplit(v.z, v.w, h1, l1);
    h[2 * i] = h0; h[2 * i + 1] = h1;
    l[2 * i] = l0; l[2 * i + 1] = l1;
}
// fp32 -> fp16 (single)
__global__ __launch_bounds__(256) void split16_kernel(const float4* __restrict__ src,
                                                      uint32_t* __restrict__ o, int n4) {
    int i = blockIdx.x * 256 + threadIdx.x;
    if (i >= n4) return;
    float4 v = src[i];
    o[2 * i]     = pack_f16x2(v.x, v.y);
    o[2 * i + 1] = pack_f16x2(v.z, v.w);
}

// ---------------- GEMM fp16 single-term: C = A @ W^T + b  -> fp16 ------------
#define F_STG 18432
__global__ __launch_bounds__(128) void gemm_f16(
    const __half* __restrict__ Ag, const __half* __restrict__ Wg,
    const float* __restrict__ bias, __half* __restrict__ Og)
{
    extern __shared__ __align__(16) char dsm[];
    const uint32_t dbase = smem_u32(dsm);
    const int m0 = blockIdx.x * 64, n0 = blockIdx.y * 64;
    const int t = threadIdx.x, warp = t >> 5, lane = t & 31;
    const int g = lane >> 2, qd = lane & 3;

    float c[8][4];
#pragma unroll
    for (int i = 0; i < 8; i++)
#pragma unroll
        for (int j = 0; j < 4; j++) c[i][j] = 0.f;

    const int lrow = t >> 1, lch = (t & 1) * 4;
    const int gmr = m0 + lrow;
    const bool mv = gmr < MROWS;
    const size_t aB = (size_t)(mv ? gmr : 0) * EM + lch * 8;
    const size_t bB = (size_t)(n0 + lrow) * EM + lch * 8;
    const uint32_t offL = (uint32_t)((lrow * 72 + lch * 8) * 2);
    const int asz = mv ? 16 : 0;
    const uint32_t aOff = (uint32_t)(((warp * 16 + (lane & 15)) * 72 + ((lane >> 4) << 3)) * 2);
    const uint32_t bOff = (uint32_t)((((lane & 7) + ((lane >> 4) << 3)) * 72 +
                                      (((lane >> 3) & 1) << 3)) * 2);

#define F_ISSUE(k0, s) do {                                                  \
        const uint32_t sb_ = dbase + (s) * F_STG;                            \
        _Pragma("unroll")                                                    \
        for (int i_ = 0; i_ < 4; i_++) {                                     \
            cpa16(sb_ + offL + i_ * 16,        Ag + aB + (k0) + i_ * 8, asz);\
            cpa16(sb_ + 9216 + offL + i_ * 16, Wg + bB + (k0) + i_ * 8, 16); \
        }                                                                    \
        cpa_commit();                                                        \
    } while (0)

    F_ISSUE(0, 0);
    F_ISSUE(64, 1);

    for (int ki = 0; ki < 8; ki++) {
        cpa_wait<1>();
        __syncthreads();
        const uint32_t sb = dbase + (ki & 1) * F_STG;
#pragma unroll
        for (int ks = 0; ks < 4; ks++) {
            uint32_t af[4];
            ldsm4(sb + aOff + ks * 32, af[0], af[1], af[2], af[3]);
#pragma unroll
            for (int np = 0; np < 4; np++) {
                uint32_t b4[4];
                ldsm4(sb + 9216 + bOff + np * 2304 + ks * 32, b4[0], b4[1], b4[2], b4[3]);
                mma_f16(c[2 * np], af, b4[0], b4[1]);
                mma_f16(c[2 * np + 1], af, b4[2], b4[3]);
            }
        }
        __syncthreads();
        if (ki + 2 < 8) { F_ISSUE((ki + 2) * 64, ki & 1); }
        else cpa_commit();
    }

    const int r0g = m0 + warp * 16 + g, r1g = r0g + 8;
#pragma unroll
    for (int nt = 0; nt < 8; nt++) {
        const int cn = n0 + nt * 8 + 2 * qd;
        const float bx = __ldg(bias + cn), by = __ldg(bias + cn + 1);
        if (r0g < MROWS)
            *(uint32_t*)(Og + (size_t)r0g * EM + cn) = pack_f16x2(c[nt][0] + bx, c[nt][1] + by);
        if (r1g < MROWS)
            *(uint32_t*)(Og + (size_t)r1g * EM + cn) = pack_f16x2(c[nt][2] + bx, c[nt][3] + by);
    }
#undef F_ISSUE
}

// ---------------- GEMM bf16 3-term (V: fp16 hi/lo out; O-proj: fp32 out) -----
#define G_STG 36864
template <int SPLIT>   // 2 = fp16 hi/lo out, 0 = fp32 out
__global__ __launch_bounds__(128) void gemm_mma(
    const __nv_bfloat16* __restrict__ Agh, const __nv_bfloat16* __restrict__ Agl,
    const __nv_bfloat16* __restrict__ Wh, const __nv_bfloat16* __restrict__ Wl,
    const float* __restrict__ bias,
    __nv_bfloat16* __restrict__ Oh, __nv_bfloat16* __restrict__ Ol,
    float* __restrict__ Of)
{
    extern __shared__ __align__(16) char dsm[];
    const uint32_t dbase = smem_u32(dsm);
    const int m0 = blockIdx.x * 64, n0 = blockIdx.y * 64;
    const int t = threadIdx.x, warp = t >> 5, lane = t & 31;
    const int g = lane >> 2, qd = lane & 3;

    float c[8][4];
#pragma unroll
    for (int i = 0; i < 8; i++)
#pragma unroll
        for (int j = 0; j < 4; j++) c[i][j] = 0.f;

    const int lrow = t >> 1, lcb = (t & 1) << 5;
    const int gmr = m0 + lrow;
    const bool mv = gmr < MROWS;
    const size_t aB = (size_t)(mv ? gmr : 0) * EM + lcb;
    const size_t bB = (size_t)(n0 + lrow) * EM + lcb;
    const uint32_t offA = (uint32_t)((lrow * 72 + lcb) * 2);
    const int asz = mv ? 16 : 0;
    const uint32_t aOff = (uint32_t)(((warp * 16 + (lane & 15)) * 72 + ((lane >> 4) << 3)) * 2);
    const uint32_t bOff = (uint32_t)((((lane & 7) + ((lane >> 4) << 3)) * 72 +
                                      (((lane >> 3) & 1) << 3)) * 2);

#define G_ISSUE(k0, s) do {                                                     \
        const uint32_t sb_ = dbase + (s) * G_STG;                               \
        _Pragma("unroll")                                                       \
        for (int i_ = 0; i_ < 4; i_++) {                                        \
            cpa16(sb_ + offA + i_ * 16,          Agh + aB + (k0) + i_ * 8, asz);\
            cpa16(sb_ + 9216 + offA + i_ * 16,   Agl + aB + (k0) + i_ * 8, asz);\
            cpa16(sb_ + 18432 + offA + i_ * 16,  Wh + bB + (k0) + i_ * 8, 16);  \
            cpa16(sb_ + 27648 + offA + i_ * 16,  Wl + bB + (k0) + i_ * 8, 16);  \
        }                                                                       \
        cpa_commit();                                                           \
    } while (0)

    G_ISSUE(0, 0);
    G_ISSUE(64, 1);

    for (int ki = 0; ki < 8; ki++) {
        cpa_wait<1>();
        __syncthreads();
        const uint32_t sb = dbase + (ki & 1) * G_STG;
        const uint32_t sAh = sb, sAl = sb + 9216, sBh = sb + 18432, sBl = sb + 27648;
#pragma unroll
        for (int ks = 0; ks < 4; ks++) {
            uint32_t ah[4], al[4];
            ldsm4(sAh + aOff + ks * 32, ah[0], ah[1], ah[2], ah[3]);
            ldsm4(sAl + aOff + ks * 32, al[0], al[1], al[2], al[3]);
#pragma unroll
            for (int np = 0; np < 4; np++) {
                uint32_t bh4[4], bl4[4];
                ldsm4(sBh + bOff + np * 2304 + ks * 32, bh4[0], bh4[1], bh4[2], bh4[3]);
                ldsm4(sBl + bOff + np * 2304 + ks * 32, bl4[0], bl4[1], bl4[2], bl4[3]);
                mma_bf(c[2 * np], ah, bh4[0], bh4[1]);
                mma_bf(c[2 * np], ah, bl4[0], bl4[1]);
                mma_bf(c[2 * np], al, bh4[0], bh4[1]);
                mma_bf(c[2 * np + 1], ah, bh4[2], bh4[3]);
                mma_bf(c[2 * np + 1], ah, bl4[2], bl4[3]);
                mma_bf(c[2 * np + 1], al, bh4[2], bh4[3]);
            }
        }
        __syncthreads();
        if (ki + 2 < 8) { G_ISSUE((ki + 2) * 64, ki & 1); }
        else cpa_commit();
    }

    const int r0g = m0 + warp * 16 + g, r1g = r0g + 8;
#pragma unroll
    for (int nt = 0; nt < 8; nt++) {
        const int cn = n0 + nt * 8 + 2 * qd;
        const float bx = __ldg(bias + cn), by = __ldg(bias + cn + 1);
        if (SPLIT == 2) {
            uint32_t hi, lo;
            if (r0g < MROWS) {
                packsplit16(c[nt][0] + bx, c[nt][1] + by, hi, lo);
                *(uint32_t*)(Oh + (size_t)r0g * EM + cn) = hi;
                *(uint32_t*)(Ol + (size_t)r0g * EM + cn) = lo;
            }
            if (r1g < MROWS) {
                packsplit16(c[nt][2] + bx, c[nt][3] + by, hi, lo);
                *(uint32_t*)(Oh + (size_t)r1g * EM + cn) = hi;
                *(uint32_t*)(Ol + (size_t)r1g * EM + cn) = lo;
            }
        } else {
            if (r0g < MROWS)
                *(float2*)(Of + (size_t)r0g * EM + cn) = make_float2(c[nt][0] + bx, c[nt][1] + by);
            if (r1g < MROWS)
                *(float2*)(Of + (size_t)r1g * EM + cn) = make_float2(c[nt][2] + bx, c[nt][3] + by);
        }
    }
#undef G_ISSUE
}

// ---------------- flash attention: 128q/CTA, fp16 S, fp16 bias ---------------
// stage: K 0 (4608) | Vh 4608 | Vl 9216 | bias 13824 (128 x 40 fp16 = 10240)
// bias row stride 40 halves = 80 B (16B multiple -> cp.async-legal)
#define A_STG 24064
__global__ __launch_bounds__(256) void attn_mma() {
    extern __shared__ __align__(16) char dsm[];
    const uint32_t dbase = smem_u32(dsm);

    const int bh = blockIdx.y;
    const int b = bh >> 3, h = bh & 7;
    const int q0 = blockIdx.x * 128;
    const int t = threadIdx.x, warp = t >> 5, lane = t & 31;
    const int g = lane >> 2, qd = lane & 3;
    const uint4 z4 = make_uint4(0, 0, 0, 0);

    // ---- phase 0: Q tile (128 x 64 fp16) to smem, hoist frags ----
    {
        const int row = t >> 1, cb = (t & 1) * 32;
        const int gq = q0 + row;
        const bool v = gq < NP_;
        const size_t base = (size_t)(b * NP_ + (v ? gq : 0)) * EM + h * DH + cb;
#pragma unroll
        for (int i = 0; i < 4; i++)
            *(uint4*)(dsm + (row * 72 + cb + i * 8) * 2) =
                v ? *(const uint4*)(g_qf + base + i * 8) : z4;
    }
    __syncthreads();
    const uint32_t qOff = (uint32_t)(((warp * 16 + (lane & 15)) * 72 + ((lane >> 4) << 3)) * 2);
    uint32_t qf[4][4];
#pragma unroll
    for (int ks = 0; ks < 4; ks++)
        ldsm4(dbase + qOff + ks * 32, qf[ks][0], qf[ks][1], qf[ks][2], qf[ks][3]);
    __syncthreads();

    // ---- pipeline mappings (256 threads) ----
    const int krow = t >> 3, kc8 = t & 7;
    const uint32_t offK = (uint32_t)((krow * 72 + kc8 * 8) * 2);
    const int frow = t >> 1, fs2 = t & 1;
    const __half* fbrow = g_fb + ((size_t)bh * NP_ + min(q0 + frow, NP_ - 1)) * FB_COLS;
    const uint32_t offFB = (uint32_t)(13824 + (frow * 40 + fs2 * 16) * 2);

#define A_ISSUE(kt, s) do {                                                        \
        const int gk_ = (kt) * 32 + krow;                                          \
        const bool v_ = gk_ < NP_;                                                 \
        const size_t gb_ = (size_t)(b * NP_ + (v_ ? gk_ : 0)) * EM + h * DH + kc8 * 8;\
        const int sz_ = v_ ? 16 : 0;                                               \
        const uint32_t sb_ = dbase + (s) * A_STG;                                  \
        cpa16(sb_ + offK,         g_kf + gb_, sz_);                                \
        cpa16(sb_ + 4608 + offK,  g_vh + gb_, sz_);                                \
        cpa16(sb_ + 9216 + offK,  g_vl + gb_, sz_);                                \
        const __half* fsrc_ = fbrow + (kt) * 32 + fs2 * 16;                        \
        cpa16f(sb_ + offFB,      fsrc_);                                           \
        cpa16f(sb_ + offFB + 16, fsrc_ + 8);                                       \
        cpa_commit();                                                              \
    } while (0)

    A_ISSUE(0, 0);
    A_ISSUE(1, 1);

    const uint32_t kOff = (uint32_t)((((lane & 7) + ((lane >> 4) << 3)) * 72 +
                                      (((lane >> 3) & 1) << 3)) * 2);
    const uint32_t vOff = (uint32_t)((((lane & 7) + (((lane >> 3) & 1) << 3)) * 72 +
                                      ((lane >> 4) << 3)) * 2);
    const int gq0 = q0 + warp * 16 + g, gq1 = gq0 + 8;
    const int r0b = (warp * 16 + g) * 40, r1b = r0b + 8 * 40;

    float m0 = -1e30f, m1 = -1e30f, l0 = 0.f, l1 = 0.f;
    float o[8][4];
#pragma unroll
    for (int i = 0; i < 8; i++)
#pragma unroll
        for (int j = 0; j < 4; j++) o[i][j] = 0.f;

    const float SSC = 0.125f * 1.44269504f;

    for (int kt = 0; kt < 33; kt++) {
        cpa_wait<1>();
        __syncthreads();
        const uint32_t sb = dbase + (kt & 1) * A_STG;
        const uint32_t sK = sb, sVh = sb + 4608, sVl = sb + 9216;
        const __half* sbias = (const __half*)(dsm + (kt & 1) * A_STG + 13824);

        // ---- S = Q K^T (fp16 single-term) ----
        float s[4][4];
#pragma unroll
        for (int i = 0; i < 4; i++)
#pragma unroll
            for (int j = 0; j < 4; j++) s[i][j] = 0.f;
#pragma unroll
        for (int ks = 0; ks < 4; ks++) {
#pragma unroll
            for (int np = 0; np < 2; np++) {
                uint32_t b4[4];
                ldsm4(sK + kOff + np * 2304 + ks * 32, b4[0], b4[1], b4[2], b4[3]);
                mma_f16(s[2 * np], qf[ks], b4[0], b4[1]);
                mma_f16(s[2 * np + 1], qf[ks], b4[2], b4[3]);
            }
        }

        // ---- fused scale + bias (log2 domain, fp16 from smem) ----
#pragma unroll
        for (int nt = 0; nt < 4; nt++) {
            const int cn = nt * 8 + 2 * qd;
            const float2 b0 = __half22float2(*(const __half2*)(sbias + r0b + cn));
            const float2 b1 = __half22float2(*(const __half2*)(sbias + r1b + cn));
            s[nt][0] = fmaf(s[nt][0], SSC, b0.x);
            s[nt][1] = fmaf(s[nt][1], SSC, b0.y);
            s[nt][2] = fmaf(s[nt][2], SSC, b1.x);
            s[nt][3] = fmaf(s[nt][3], SSC, b1.y);
        }

        // ---- online softmax (base 2) ----
        float lm0 = -1e30f, lm1 = -1e30f;
#pragma unroll
        for (int nt = 0; nt < 4; nt++) {
            lm0 = fmaxf(lm0, fmaxf(s[nt][0], s[nt][1]));
            lm1 = fmaxf(lm1, fmaxf(s[nt][2], s[nt][3]));
        }
        lm0 = fmaxf(lm0, __shfl_xor_sync(0xffffffffu, lm0, 1));
        lm0 = fmaxf(lm0, __shfl_xor_sync(0xffffffffu, lm0, 2));
        lm1 = fmaxf(lm1, __shfl_xor_sync(0xffffffffu, lm1, 1));
        lm1 = fmaxf(lm1, __shfl_xor_sync(0xffffffffu, lm1, 2));
        const float mn0 = fmaxf(m0, lm0), mn1 = fmaxf(m1, lm1);
        const float sc0 = fexp2(m0 - mn0), sc1 = fexp2(m1 - mn1);
        m0 = mn0; m1 = mn1;

        float ps0 = 0.f, ps1 = 0.f;
#pragma unroll
        for (int nt = 0; nt < 4; nt++) {
            s[nt][0] = fexp2(s[nt][0] - mn0);
            s[nt][1] = fexp2(s[nt][1] - mn0);
            s[nt][2] = fexp2(s[nt][2] - mn1);
            s[nt][3] = fexp2(s[nt][3] - mn1);
            ps0 += s[nt][0] + s[nt][1];
            ps1 += s[nt][2] + s[nt][3];
        }
        ps0 += __shfl_xor_sync(0xffffffffu, ps0, 1);
        ps0 += __shfl_xor_sync(0xffffffffu, ps0, 2);
        ps1 += __shfl_xor_sync(0xffffffffu, ps1, 1);
        ps1 += __shfl_xor_sync(0xffffffffu, ps1, 2);
        l0 = l0 * sc0 + ps0;
        l1 = l1 * sc1 + ps1;

        // ---- P -> fp16 A-frags, rescale O ----
        uint32_t ap[2][4];
#pragma unroll
        for (int ks = 0; ks < 2; ks++) {
            ap[ks][0] = pack_f16x2(s[2 * ks][0], s[2 * ks][1]);
            ap[ks][1] = pack_f16x2(s[2 * ks][2], s[2 * ks][3]);
            ap[ks][2] = pack_f16x2(s[2 * ks + 1][0], s[2 * ks + 1][1]);
            ap[ks][3] = pack_f16x2(s[2 * ks + 1][2], s[2 * ks + 1][3]);
        }
#pragma unroll
        for (int nt = 0; nt < 8; nt++) {
            o[nt][0] *= sc0; o[nt][1] *= sc0;
            o[nt][2] *= sc1; o[nt][3] *= sc1;
        }

        // ---- O += P V (fp16, V hi+lo) ----
#pragma unroll
        for (int ks = 0; ks < 2; ks++) {
#pragma unroll
            for (int dp = 0; dp < 4; dp++) {
                uint32_t vh4[4], vl4[4];
                ldsm4t(sVh + vOff + ks * 2304 + dp * 32, vh4[0], vh4[1], vh4[2], vh4[3]);
                ldsm4t(sVl + vOff + ks * 2304 + dp * 32, vl4[0], vl4[1], vl4[2], vl4[3]);
                mma_f16(o[2 * dp], ap[ks], vh4[0], vh4[1]);
                mma_f16(o[2 * dp], ap[ks], vl4[0], vl4[1]);
                mma_f16(o[2 * dp + 1], ap[ks], vh4[2], vh4[3]);
                mma_f16(o[2 * dp + 1], ap[ks], vl4[2], vl4[3]);
            }
        }

        __syncthreads();
        if (kt + 2 < 33) { A_ISSUE(kt + 2, kt & 1); }
        else cpa_commit();
    }

    // ---- finalize: ctx = O / l, split-bf16 write ----
    const float i0 = (l0 > 0.f) ? 1.f / l0 : 0.f;
    const float i1 = (l1 > 0.f) ? 1.f / l1 : 0.f;
#pragma unroll
    for (int nt = 0; nt < 8; nt++) {
        const int d0 = h * DH + nt * 8 + 2 * qd;
        uint32_t hi, lo;
        if (gq0 < NP_) {
            packsplit(o[nt][0] * i0, o[nt][1] * i0, hi, lo);
            const size_t off = (size_t)(b * NP_ + gq0) * EM + d0;
            *(uint32_t*)(g_ch + off) = hi; *(uint32_t*)(g_cl + off) = lo;
        }
        if (gq1 < NP_) {
            packsplit(o[nt][2] * i1, o[nt][3] * i1, hi, lo);
            const size_t off = (size_t)(b * NP_ + gq1) * EM + d0;
            *(uint32_t*)(g_ch + off) = hi; *(uint32_t*)(g_cl + off) = lo;
        }
    }
#undef A_ISSUE
}

// ---------------------------------------------------------------------------
extern "C" void kernel_launch(void* const* d_in, const int* in_sizes, int n_in,
                              void* d_out, int out_size)
{
    const float* x = (const float*)d_in[0];
    const float* abias = (const float*)d_in[1];
    const void* pmask = (const void*)d_in[2];
    const float* Ws[4] = {(const float*)d_in[3], (const float*)d_in[5],
                          (const float*)d_in[7], (const float*)d_in[9]};
    const float* bs[4] = {(const float*)d_in[4], (const float*)d_in[6],
                          (const float*)d_in[8], (const float*)d_in[10]};
    float* out = (float*)d_out;

    void *xh, *xl, *wh, *wl, *xf, *wqf, *wkf, *qfp, *kfp, *vh, *vl, *ch, *cl;
    cudaGetSymbolAddress(&xh, g_xh); cudaGetSymbolAddress(&xl, g_xl);
    cudaGetSymbolAddress(&wh, g_wh); cudaGetSymbolAddress(&wl, g_wl);
    cudaGetSymbolAddress(&xf, g_xf); cudaGetSymbolAddress(&wqf, g_wqf);
    cudaGetSymbolAddress(&wkf, g_wkf);
    cudaGetSymbolAddress(&qfp, g_qf); cudaGetSymbolAddress(&kfp, g_kf);
    cudaGetSymbolAddress(&vh, g_vh); cudaGetSymbolAddress(&vl, g_vl);
    cudaGetSymbolAddress(&ch, g_ch); cudaGetSymbolAddress(&cl, g_cl);

    cudaFuncSetAttribute(gemm_f16, cudaFuncAttributeMaxDynamicSharedMemorySize, 2 * F_STG);
    cudaFuncSetAttribute(gemm_mma<2>, cudaFuncAttributeMaxDynamicSharedMemorySize, 2 * G_STG);
    cudaFuncSetAttribute(gemm_mma<0>, cudaFuncAttributeMaxDynamicSharedMemorySize, 2 * G_STG);
    cudaFuncSetAttribute(attn_mma, cudaFuncAttributeMaxDynamicSharedMemorySize, 2 * A_STG);

    mask_detect_kernel<<<1, 32>>>((const unsigned int*)pmask);
    {
        const size_t total = (size_t)NB * NH * NP_ * (FB_COLS / 8);
        fuse_kernel<<<(unsigned)((total + 255) / 256), 256>>>(abias, pmask);
    }

    // fp16 singles for Q/K path
    split16_kernel<<<(XE / 4 + 255) / 256, 256>>>((const float4*)x, (uint32_t*)xf, XE / 4);
    split16_kernel<<<WE / 4 / 256, 256>>>((const float4*)Ws[0], (uint32_t*)wqf, WE / 4);
    split16_kernel<<<WE / 4 / 256, 256>>>((const float4*)Ws[1], (uint32_t*)wkf, WE / 4);
    // bf16 hi/lo for V and O-proj paths
    split_kernel<<<(XE / 4 + 255) / 256, 256>>>((const float4*)x,
        (uint32_t*)xh, (uint32_t*)xl, XE / 4);
    split_kernel<<<WE / 4 / 256, 256>>>((const float4*)Ws[2],
        (uint32_t*)((__nv_bfloat16*)wh + (size_t)2 * WE),
        (uint32_t*)((__nv_bfloat16*)wl + (size_t)2 * WE), WE / 4);
    split_kernel<<<WE / 4 / 256, 256>>>((const float4*)Ws[3],
        (uint32_t*)((__nv_bfloat16*)wh + (size_t)3 * WE),
        (uint32_t*)((__nv_bfloat16*)wl + (size_t)3 * WE), WE / 4);

    dim3 gg(129, 8);
    gemm_f16<<<gg, 128, 2 * F_STG>>>((const __half*)xf, (const __half*)wqf, bs[0], (__half*)qfp);
    gemm_f16<<<gg, 128, 2 * F_STG>>>((const __half*)xf, (const __half*)wkf, bs[1], (__half*)kfp);
    gemm_mma<2><<<gg, 128, 2 * G_STG>>>((const __nv_bfloat16*)xh, (const __nv_bfloat16*)xl,
        (const __nv_bfloat16*)wh + (size_t)2 * WE, (const __nv_bfloat16*)wl + (size_t)2 * WE, bs[2],
        (__nv_bfloat16*)vh, (__nv_bfloat16*)vl, nullptr);

    attn_mma<<<dim3(9, 64), 256, 2 * A_STG>>>();

    gemm_mma<0><<<gg, 128, 2 * G_STG>>>((const __nv_bfloat16*)ch, (const __nv_bfloat16*)cl,
        (const __nv_bfloat16*)wh + (size_t)3 * WE, (const __nv_bfloat16*)wl + (size_t)3 * WE, bs[3],
        nullptr, nullptr, out);
}

// round 16
// speedup vs baseline: 5.2094x; 1.0146x over previous
#include <cuda_runtime.h>
#include <cuda_bf16.h>
#include <cuda_fp16.h>
#include <math.h>
#include <stdint.h>

#define NB 8
#define NH 8
#define NP_ 1025
#define NPAD 1024
#define DH 64
#define EM 512
#define MROWS (NB * NP_)
#define XE (MROWS * EM)
#define WE (EM * EM)
#define FB_COLS 1088

__device__ __align__(16) __nv_bfloat16 g_xh[XE], g_xl[XE];
__device__ __align__(16) __nv_bfloat16 g_wh[4][WE], g_wl[4][WE];
__device__ __align__(16) __half g_xf[XE], g_wqf[WE], g_wkf[WE];
__device__ __align__(16) __half g_qf[XE], g_kf[XE], g_vf[XE];
__device__ __align__(16) __nv_bfloat16 g_ch[XE], g_cl[XE];
__device__ __align__(16) __half g_fb[(size_t)NB * NH * NP_ * FB_COLS];
__device__ int g_mask_mode;

// ---------------- helpers ---------------------------------------------------
__device__ __forceinline__ uint32_t smem_u32(const void* p) {
    return (uint32_t)__cvta_generic_to_shared(p);
}
__device__ __forceinline__ void ldsm4(uint32_t a, uint32_t& r0, uint32_t& r1,
                                      uint32_t& r2, uint32_t& r3) {
    asm volatile("ldmatrix.sync.aligned.m8n8.x4.shared.b16 {%0,%1,%2,%3},[%4];"
                 : "=r"(r0), "=r"(r1), "=r"(r2), "=r"(r3) : "r"(a));
}
__device__ __forceinline__ void ldsm4t(uint32_t a, uint32_t& r0, uint32_t& r1,
                                       uint32_t& r2, uint32_t& r3) {
    asm volatile("ldmatrix.sync.aligned.m8n8.x4.trans.shared.b16 {%0,%1,%2,%3},[%4];"
                 : "=r"(r0), "=r"(r1), "=r"(r2), "=r"(r3) : "r"(a));
}
__device__ __forceinline__ void mma_bf(float* c, const uint32_t* a, uint32_t b0, uint32_t b1) {
    asm volatile(
        "mma.sync.aligned.m16n8k16.row.col.f32.bf16.bf16.f32 "
        "{%0,%1,%2,%3},{%4,%5,%6,%7},{%8,%9},{%0,%1,%2,%3};"
        : "+f"(c[0]), "+f"(c[1]), "+f"(c[2]), "+f"(c[3])
        : "r"(a[0]), "r"(a[1]), "r"(a[2]), "r"(a[3]), "r"(b0), "r"(b1));
}
__device__ __forceinline__ void mma_f16(float* c, const uint32_t* a, uint32_t b0, uint32_t b1) {
    asm volatile(
        "mma.sync.aligned.m16n8k16.row.col.f32.f16.f16.f32 "
        "{%0,%1,%2,%3},{%4,%5,%6,%7},{%8,%9},{%0,%1,%2,%3};"
        : "+f"(c[0]), "+f"(c[1]), "+f"(c[2]), "+f"(c[3])
        : "r"(a[0]), "r"(a[1]), "r"(a[2]), "r"(a[3]), "r"(b0), "r"(b1));
}
__device__ __forceinline__ void packsplit(float a, float b, uint32_t& hi, uint32_t& lo) {
    __nv_bfloat16 ha = __float2bfloat16(a), hb = __float2bfloat16(b);
    __nv_bfloat16 la = __float2bfloat16(a - __bfloat162float(ha));
    __nv_bfloat16 lb = __float2bfloat16(b - __bfloat162float(hb));
    __nv_bfloat162 H = __halves2bfloat162(ha, hb), L = __halves2bfloat162(la, lb);
    hi = *(uint32_t*)&H; lo = *(uint32_t*)&L;
}
__device__ __forceinline__ uint32_t pack_f16x2(float lo, float hi) {
    uint32_t r;
    asm("cvt.rn.f16x2.f32 %0,%1,%2;" : "=r"(r) : "f"(hi), "f"(lo));
    return r;
}
__device__ __forceinline__ float fexp2(float x) {
    float r;
    asm("ex2.approx.ftz.f32 %0,%1;" : "=f"(r) : "f"(x));
    return r;
}
__device__ __forceinline__ void cpa16(uint32_t dst, const void* src, int sz) {
    asm volatile("cp.async.cg.shared.global [%0], [%1], 16, %2;"
                 :: "r"(dst), "l"(src), "r"(sz));
}
__device__ __forceinline__ void cpa16f(uint32_t dst, const void* src) {
    asm volatile("cp.async.cg.shared.global [%0], [%1], 16;"
                 :: "r"(dst), "l"(src));
}
__device__ __forceinline__ void cpa_commit() {
    asm volatile("cp.async.commit_group;");
}
template <int N> __device__ __forceinline__ void cpa_wait() {
    asm volatile("cp.async.wait_group %0;" :: "n"(N));
}

// ---------------- mask dtype detect -----------------------------------------
__global__ void mask_detect_kernel(const unsigned int* __restrict__ pm) {
    int t = threadIdx.x;
    bool aF = true, aI = true;
    for (int i = t; i < 4096; i += 32) {
        unsigned int w = pm[i];
        if (!(w == 0u || w == 0x3F800000u)) aF = false;
        if (w > 1u) aI = false;
    }
    aF = __all_sync(0xffffffffu, aF);
    aI = __all_sync(0xffffffffu, aI);
    if (t == 0) g_mask_mode = aF ? 0 : (aI ? 1 : 2);
}

// ---------------- fused bias+mask in fp16 (log2 domain) ----------------------
__global__ __launch_bounds__(256) void fuse_kernel(const float* __restrict__ abias,
                                                   const void* __restrict__ pm) {
    const size_t total = (size_t)NB * NH * NP_ * (FB_COLS / 8);
    size_t idx = (size_t)blockIdx.x * 256 + threadIdx.x;
    if (idx >= total) return;
    const int c8 = (int)(idx % (FB_COLS / 8));
    const size_t rq = idx / (FB_COLS / 8);
    const int q = (int)(rq % NP_);
    const int bh = (int)(rq / NP_);
    const int b = bh >> 3;
    const int mode = g_mask_mode;
    const float* arow = abias + rq * NP_;
    __half out[8];
#pragma unroll
    for (int j = 0; j < 8; j++) {
        const int c = c8 * 8 + j;
        float v = -60000.f;
        if (c < NP_) {
            bool ok = (q == 0) || (c == 0);
            if (!ok) {
                const size_t mi = ((size_t)b * NPAD + (q - 1)) * NPAD + (c - 1);
                if (mode == 0)      ok = ((const float*)pm)[mi] != 0.f;
                else if (mode == 1) ok = ((const int*)pm)[mi] != 0;
                else                ok = ((const unsigned char*)pm)[mi] != 0;
            }
            if (ok) v = arow[c] * 1.44269504f;
        }
        out[j] = __float2half_rn(v);
    }
    *(uint4*)(g_fb + rq * FB_COLS + c8 * 8) = *(uint4*)out;
}

// ---------------- fp32 -> bf16 hi/lo split ----------------------------------
__global__ __launch_bounds__(256) void split_kernel(const float4* __restrict__ src,
                                                    uint32_t* __restrict__ h,
                                                    uint32_t* __restrict__ l,
                                                    int n4) {
    int i = blockIdx.x * 256 + threadIdx.x;
    if (i >= n4) return;
    float4 v = src[i];
    uint32_t h0, l0, h1, l1;
    packsplit(v.x, v.y, h0, l0);
    packsplit(v.z, v.w, h1, l1);
    h[2 * i] = h0; h[2 * i + 1] = h1;
    l[2 * i] = l0; l[2 * i + 1] = l1;
}
// fp32 -> fp16 (single)
__global__ __launch_bounds__(256) void split16_kernel(const float4* __restrict__ src,
                                                      uint32_t* __restrict__ o, int n4) {
    int i = blockIdx.x * 256 + threadIdx.x;
    if (i >= n4) return;
    float4 v = src[i];
    o[2 * i]     = pack_f16x2(v.x, v.y);
    o[2 * i + 1] = pack_f16x2(v.z, v.w);
}

// ---------------- GEMM fp16 single-term: C = A @ W^T + b  -> fp16 ------------
#define F_STG 18432
__global__ __launch_bounds__(128) void gemm_f16(
    const __half* __restrict__ Ag, const __half* __restrict__ Wg,
    const float* __restrict__ bias, __half* __restrict__ Og)
{
    extern __shared__ __align__(16) char dsm[];
    const uint32_t dbase = smem_u32(dsm);
    const int m0 = blockIdx.x * 64, n0 = blockIdx.y * 64;
    const int t = threadIdx.x, warp = t >> 5, lane = t & 31;
    const int g = lane >> 2, qd = lane & 3;

    float c[8][4];
#pragma unroll
    for (int i = 0; i < 8; i++)
#pragma unroll
        for (int j = 0; j < 4; j++) c[i][j] = 0.f;

    const int lrow = t >> 1, lch = (t & 1) * 4;
    const int gmr = m0 + lrow;
    const bool mv = gmr < MROWS;
    const size_t aB = (size_t)(mv ? gmr : 0) * EM + lch * 8;
    const size_t bB = (size_t)(n0 + lrow) * EM + lch * 8;
    const uint32_t offL = (uint32_t)((lrow * 72 + lch * 8) * 2);
    const int asz = mv ? 16 : 0;
    const uint32_t aOff = (uint32_t)(((warp * 16 + (lane & 15)) * 72 + ((lane >> 4) << 3)) * 2);
    const uint32_t bOff = (uint32_t)((((lane & 7) + ((lane >> 4) << 3)) * 72 +
                                      (((lane >> 3) & 1) << 3)) * 2);

#define F_ISSUE(k0, s) do {                                                  \
        const uint32_t sb_ = dbase + (s) * F_STG;                            \
        _Pragma("unroll")                                                    \
        for (int i_ = 0; i_ < 4; i_++) {                                     \
            cpa16(sb_ + offL + i_ * 16,        Ag + aB + (k0) + i_ * 8, asz);\
            cpa16(sb_ + 9216 + offL + i_ * 16, Wg + bB + (k0) + i_ * 8, 16); \
        }                                                                    \
        cpa_commit();                                                        \
    } while (0)

    F_ISSUE(0, 0);
    F_ISSUE(64, 1);

    for (int ki = 0; ki < 8; ki++) {
        cpa_wait<1>();
        __syncthreads();
        const uint32_t sb = dbase + (ki & 1) * F_STG;
#pragma unroll
        for (int ks = 0; ks < 4; ks++) {
            uint32_t af[4];
            ldsm4(sb + aOff + ks * 32, af[0], af[1], af[2], af[3]);
#pragma unroll
            for (int np = 0; np < 4; np++) {
                uint32_t b4[4];
                ldsm4(sb + 9216 + bOff + np * 2304 + ks * 32, b4[0], b4[1], b4[2], b4[3]);
                mma_f16(c[2 * np], af, b4[0], b4[1]);
                mma_f16(c[2 * np + 1], af, b4[2], b4[3]);
            }
        }
        __syncthreads();
        if (ki + 2 < 8) { F_ISSUE((ki + 2) * 64, ki & 1); }
        else cpa_commit();
    }

    const int r0g = m0 + warp * 16 + g, r1g = r0g + 8;
#pragma unroll
    for (int nt = 0; nt < 8; nt++) {
        const int cn = n0 + nt * 8 + 2 * qd;
        const float bx = __ldg(bias + cn), by = __ldg(bias + cn + 1);
        if (r0g < MROWS)
            *(uint32_t*)(Og + (size_t)r0g * EM + cn) = pack_f16x2(c[nt][0] + bx, c[nt][1] + by);
        if (r1g < MROWS)
            *(uint32_t*)(Og + (size_t)r1g * EM + cn) = pack_f16x2(c[nt][2] + bx, c[nt][3] + by);
    }
#undef F_ISSUE
}

// ---------------- GEMM bf16 3-term (SPLIT 3 = fp16 single out, 0 = fp32 out) -
#define G_STG 36864
template <int SPLIT>
__global__ __launch_bounds__(128) void gemm_mma(
    const __nv_bfloat16* __restrict__ Agh, const __nv_bfloat16* __restrict__ Agl,
    const __nv_bfloat16* __restrict__ Wh, const __nv_bfloat16* __restrict__ Wl,
    const float* __restrict__ bias,
    __half* __restrict__ Og, float* __restrict__ Of)
{
    extern __shared__ __align__(16) char dsm[];
    const uint32_t dbase = smem_u32(dsm);
    const int m0 = blockIdx.x * 64, n0 = blockIdx.y * 64;
    const int t = threadIdx.x, warp = t >> 5, lane = t & 31;
    const int g = lane >> 2, qd = lane & 3;

    float c[8][4];
#pragma unroll
    for (int i = 0; i < 8; i++)
#pragma unroll
        for (int j = 0; j < 4; j++) c[i][j] = 0.f;

    const int lrow = t >> 1, lcb = (t & 1) << 5;
    const int gmr = m0 + lrow;
    const bool mv = gmr < MROWS;
    const size_t aB = (size_t)(mv ? gmr : 0) * EM + lcb;
    const size_t bB = (size_t)(n0 + lrow) * EM + lcb;
    const uint32_t offA = (uint32_t)((lrow * 72 + lcb) * 2);
    const int asz = mv ? 16 : 0;
    const uint32_t aOff = (uint32_t)(((warp * 16 + (lane & 15)) * 72 + ((lane >> 4) << 3)) * 2);
    const uint32_t bOff = (uint32_t)((((lane & 7) + ((lane >> 4) << 3)) * 72 +
                                      (((lane >> 3) & 1) << 3)) * 2);

#define G_ISSUE(k0, s) do {                                                     \
        const uint32_t sb_ = dbase + (s) * G_STG;                               \
        _Pragma("unroll")                                                       \
        for (int i_ = 0; i_ < 4; i_++) {                                        \
            cpa16(sb_ + offA + i_ * 16,          Agh + aB + (k0) + i_ * 8, asz);\
            cpa16(sb_ + 9216 + offA + i_ * 16,   Agl + aB + (k0) + i_ * 8, asz);\
            cpa16(sb_ + 18432 + offA + i_ * 16,  Wh + bB + (k0) + i_ * 8, 16);  \
            cpa16(sb_ + 27648 + offA + i_ * 16,  Wl + bB + (k0) + i_ * 8, 16);  \
        }                                                                       \
        cpa_commit();                                                           \
    } while (0)

    G_ISSUE(0, 0);
    G_ISSUE(64, 1);

    for (int ki = 0; ki < 8; ki++) {
        cpa_wait<1>();
        __syncthreads();
        const uint32_t sb = dbase + (ki & 1) * G_STG;
        const uint32_t sAh = sb, sAl = sb + 9216, sBh = sb + 18432, sBl = sb + 27648;
#pragma unroll
        for (int ks = 0; ks < 4; ks++) {
            uint32_t ah[4], al[4];
            ldsm4(sAh + aOff + ks * 32, ah[0], ah[1], ah[2], ah[3]);
            ldsm4(sAl + aOff + ks * 32, al[0], al[1], al[2], al[3]);
#pragma unroll
            for (int np = 0; np < 4; np++) {
                uint32_t bh4[4], bl4[4];
                ldsm4(sBh + bOff + np * 2304 + ks * 32, bh4[0], bh4[1], bh4[2], bh4[3]);
                ldsm4(sBl + bOff + np * 2304 + ks * 32, bl4[0], bl4[1], bl4[2], bl4[3]);
                mma_bf(c[2 * np], ah, bh4[0], bh4[1]);
                mma_bf(c[2 * np], ah, bl4[0], bl4[1]);
                mma_bf(c[2 * np], al, bh4[0], bh4[1]);
                mma_bf(c[2 * np + 1], ah, bh4[2], bh4[3]);
                mma_bf(c[2 * np + 1], ah, bl4[2], bl4[3]);
                mma_bf(c[2 * np + 1], al, bh4[2], bh4[3]);
            }
        }
        __syncthreads();
        if (ki + 2 < 8) { G_ISSUE((ki + 2) * 64, ki & 1); }
        else cpa_commit();
    }

    const int r0g = m0 + warp * 16 + g, r1g = r0g + 8;
#pragma unroll
    for (int nt = 0; nt < 8; nt++) {
        const int cn = n0 + nt * 8 + 2 * qd;
        const float bx = __ldg(bias + cn), by = __ldg(bias + cn + 1);
        if (SPLIT == 3) {
            if (r0g < MROWS)
                *(uint32_t*)(Og + (size_t)r0g * EM + cn) =
                    pack_f16x2(c[nt][0] + bx, c[nt][1] + by);
            if (r1g < MROWS)
                *(uint32_t*)(Og + (size_t)r1g * EM + cn) =
                    pack_f16x2(c[nt][2] + bx, c[nt][3] + by);
        } else {
            if (r0g < MROWS)
                *(float2*)(Of + (size_t)r0g * EM + cn) = make_float2(c[nt][0] + bx, c[nt][1] + by);
            if (r1g < MROWS)
                *(float2*)(Of + (size_t)r1g * EM + cn) = make_float2(c[nt][2] + bx, c[nt][3] + by);
        }
    }
#undef G_ISSUE
}

// ---------------- flash attention: 128q/CTA, 64-key tiles, fp16 all ----------
// stage: K 0 (64x72x2=9216) | V 9216 (9216) | bias 18432 (128x64 fp16 = 16384)
#define A_STG 34816
__global__ __launch_bounds__(256) void attn_mma() {
    extern __shared__ __align__(16) char dsm[];
    const uint32_t dbase = smem_u32(dsm);

    const int bh = blockIdx.y;
    const int b = bh >> 3, h = bh & 7;
    const int q0 = blockIdx.x * 128;
    const int t = threadIdx.x, warp = t >> 5, lane = t & 31;
    const int g = lane >> 2, qd = lane & 3;
    const uint4 z4 = make_uint4(0, 0, 0, 0);

    // ---- phase 0: Q tile (128 x 64 fp16) to smem, hoist frags ----
    {
        const int row = t >> 1, cb = (t & 1) * 32;
        const int gq = q0 + row;
        const bool v = gq < NP_;
        const size_t base = (size_t)(b * NP_ + (v ? gq : 0)) * EM + h * DH + cb;
#pragma unroll
        for (int i = 0; i < 4; i++)
            *(uint4*)(dsm + (row * 72 + cb + i * 8) * 2) =
                v ? *(const uint4*)(g_qf + base + i * 8) : z4;
    }
    __syncthreads();
    const uint32_t qOff = (uint32_t)(((warp * 16 + (lane & 15)) * 72 + ((lane >> 4) << 3)) * 2);
    uint32_t qf[4][4];
#pragma unroll
    for (int ks = 0; ks < 4; ks++)
        ldsm4(dbase + qOff + ks * 32, qf[ks][0], qf[ks][1], qf[ks][2], qf[ks][3]);
    __syncthreads();

    // ---- pipeline mappings (256 threads, 64-key tiles) ----
    const int krow = t >> 2, kc = (t & 3) * 16;          // K/V: 64 rows, 16 halves each
    const uint32_t offK = (uint32_t)((krow * 72 + kc) * 2);
    const int frow = t >> 1, fs = (t & 1) * 32;          // bias: 128 rows, 32 halves each
    const __half* fbrow = g_fb + ((size_t)bh * NP_ + min(q0 + frow, NP_ - 1)) * FB_COLS;
    const uint32_t offFB = (uint32_t)(18432 + (frow * 64 + fs) * 2);

#define A_ISSUE(kt, s) do {                                                        \
        const int gk_ = (kt) * 64 + krow;                                          \
        const bool v_ = gk_ < NP_;                                                 \
        const size_t gb_ = (size_t)(b * NP_ + (v_ ? gk_ : 0)) * EM + h * DH + kc;  \
        const int sz_ = v_ ? 16 : 0;                                               \
        const uint32_t sb_ = dbase + (s) * A_STG;                                  \
        cpa16(sb_ + offK,              g_kf + gb_, sz_);                           \
        cpa16(sb_ + offK + 16,         g_kf + gb_ + 8, sz_);                       \
        cpa16(sb_ + 9216 + offK,       g_vf + gb_, sz_);                           \
        cpa16(sb_ + 9216 + offK + 16,  g_vf + gb_ + 8, sz_);                       \
        const __half* fsrc_ = fbrow + (kt) * 64 + fs;                              \
        _Pragma("unroll")                                                          \
        for (int j_ = 0; j_ < 4; j_++)                                             \
            cpa16f(offFB + sb_ + j_ * 16, fsrc_ + j_ * 8);                         \
        cpa_commit();                                                              \
    } while (0)

    A_ISSUE(0, 0);
    A_ISSUE(1, 1);

    const uint32_t kOff = (uint32_t)((((lane & 7) + ((lane >> 4) << 3)) * 72 +
                                      (((lane >> 3) & 1) << 3)) * 2);
    const uint32_t vOff = (uint32_t)((((lane & 7) + (((lane >> 3) & 1) << 3)) * 72 +
                                      ((lane >> 4) << 3)) * 2);
    const int gq0 = q0 + warp * 16 + g, gq1 = gq0 + 8;
    const int r0b = (warp * 16 + g) * 64, r1b = r0b + 8 * 64;

    float m0 = -1e30f, m1 = -1e30f, l0 = 0.f, l1 = 0.f;
    float o[8][4];
#pragma unroll
    for (int i = 0; i < 8; i++)
#pragma unroll
        for (int j = 0; j < 4; j++) o[i][j] = 0.f;

    const float SSC = 0.125f * 1.44269504f;

    for (int kt = 0; kt < 17; kt++) {
        cpa_wait<1>();
        __syncthreads();
        const uint32_t sb = dbase + (kt & 1) * A_STG;
        const uint32_t sK = sb, sV = sb + 9216;
        const __half* sbias = (const __half*)(dsm + (kt & 1) * A_STG + 18432);

        // ---- S = Q K^T (fp16, 16q x 64k per warp) ----
        float s[8][4];
#pragma unroll
        for (int i = 0; i < 8; i++)
#pragma unroll
            for (int j = 0; j < 4; j++) s[i][j] = 0.f;
#pragma unroll
        for (int ks = 0; ks < 4; ks++) {
#pragma unroll
            for (int np = 0; np < 4; np++) {
                uint32_t b4[4];
                ldsm4(sK + kOff + np * 2304 + ks * 32, b4[0], b4[1], b4[2], b4[3]);
                mma_f16(s[2 * np], qf[ks], b4[0], b4[1]);
                mma_f16(s[2 * np + 1], qf[ks], b4[2], b4[3]);
            }
        }

        // ---- fused scale + bias (log2 domain, fp16 from smem) ----
#pragma unroll
        for (int nt = 0; nt < 8; nt++) {
            const int cn = nt * 8 + 2 * qd;
            const float2 b0 = __half22float2(*(const __half2*)(sbias + r0b + cn));
            const float2 b1 = __half22float2(*(const __half2*)(sbias + r1b + cn));
            s[nt][0] = fmaf(s[nt][0], SSC, b0.x);
            s[nt][1] = fmaf(s[nt][1], SSC, b0.y);
            s[nt][2] = fmaf(s[nt][2], SSC, b1.x);
            s[nt][3] = fmaf(s[nt][3], SSC, b1.y);
        }

        // ---- online softmax (base 2) ----
        float lm0 = -1e30f, lm1 = -1e30f;
#pragma unroll
        for (int nt = 0; nt < 8; nt++) {
            lm0 = fmaxf(lm0, fmaxf(s[nt][0], s[nt][1]));
            lm1 = fmaxf(lm1, fmaxf(s[nt][2], s[nt][3]));
        }
        lm0 = fmaxf(lm0, __shfl_xor_sync(0xffffffffu, lm0, 1));
        lm0 = fmaxf(lm0, __shfl_xor_sync(0xffffffffu, lm0, 2));
        lm1 = fmaxf(lm1, __shfl_xor_sync(0xffffffffu, lm1, 1));
        lm1 = fmaxf(lm1, __shfl_xor_sync(0xffffffffu, lm1, 2));
        const float mn0 = fmaxf(m0, lm0), mn1 = fmaxf(m1, lm1);
        const float sc0 = fexp2(m0 - mn0), sc1 = fexp2(m1 - mn1);
        m0 = mn0; m1 = mn1;

        float ps0 = 0.f, ps1 = 0.f;
#pragma unroll
        for (int nt = 0; nt < 8; nt++) {
            s[nt][0] = fexp2(s[nt][0] - mn0);
            s[nt][1] = fexp2(s[nt][1] - mn0);
            s[nt][2] = fexp2(s[nt][2] - mn1);
            s[nt][3] = fexp2(s[nt][3] - mn1);
            ps0 += s[nt][0] + s[nt][1];
            ps1 += s[nt][2] + s[nt][3];
        }
        ps0 += __shfl_xor_sync(0xffffffffu, ps0, 1);
        ps0 += __shfl_xor_sync(0xffffffffu, ps0, 2);
        ps1 += __shfl_xor_sync(0xffffffffu, ps1, 1);
        ps1 += __shfl_xor_sync(0xffffffffu, ps1, 2);
        l0 = l0 * sc0 + ps0;
        l1 = l1 * sc1 + ps1;

        // ---- P -> fp16 A-frags (4 k-groups of 16), rescale O ----
        uint32_t ap[4][4];
#pragma unroll
        for (int kp = 0; kp < 4; kp++) {
            ap[kp][0] = pack_f16x2(s[2 * kp][0], s[2 * kp][1]);
            ap[kp][1] = pack_f16x2(s[2 * kp][2], s[2 * kp][3]);
            ap[kp][2] = pack_f16x2(s[2 * kp + 1][0], s[2 * kp + 1][1]);
            ap[kp][3] = pack_f16x2(s[2 * kp + 1][2], s[2 * kp + 1][3]);
        }
#pragma unroll
        for (int nt = 0; nt < 8; nt++) {
            o[nt][0] *= sc0; o[nt][1] *= sc0;
            o[nt][2] *= sc1; o[nt][3] *= sc1;
        }

        // ---- O += P V (fp16 single) ----
#pragma unroll
        for (int kp = 0; kp < 4; kp++) {
#pragma unroll
            for (int dp = 0; dp < 4; dp++) {
                uint32_t v4[4];
                ldsm4t(sV + vOff + kp * 2304 + dp * 32, v4[0], v4[1], v4[2], v4[3]);
                mma_f16(o[2 * dp], ap[kp], v4[0], v4[1]);
                mma_f16(o[2 * dp + 1], ap[kp], v4[2], v4[3]);
            }
        }

        __syncthreads();
        if (kt + 2 < 17) { A_ISSUE(kt + 2, kt & 1); }
        else cpa_commit();
    }

    // ---- finalize: ctx = O / l, split-bf16 write ----
    const float i0 = (l0 > 0.f) ? 1.f / l0 : 0.f;
    const float i1 = (l1 > 0.f) ? 1.f / l1 : 0.f;
#pragma unroll
    for (int nt = 0; nt < 8; nt++) {
        const int d0 = h * DH + nt * 8 + 2 * qd;
        uint32_t hi, lo;
        if (gq0 < NP_) {
            packsplit(o[nt][0] * i0, o[nt][1] * i0, hi, lo);
            const size_t off = (size_t)(b * NP_ + gq0) * EM + d0;
            *(uint32_t*)(g_ch + off) = hi; *(uint32_t*)(g_cl + off) = lo;
        }
        if (gq1 < NP_) {
            packsplit(o[nt][2] * i1, o[nt][3] * i1, hi, lo);
            const size_t off = (size_t)(b * NP_ + gq1) * EM + d0;
            *(uint32_t*)(g_ch + off) = hi; *(uint32_t*)(g_cl + off) = lo;
        }
    }
#undef A_ISSUE
}

// ---------------------------------------------------------------------------
extern "C" void kernel_launch(void* const* d_in, const int* in_sizes, int n_in,
                              void* d_out, int out_size)
{
    const float* x = (const float*)d_in[0];
    const float* abias = (const float*)d_in[1];
    const void* pmask = (const void*)d_in[2];
    const float* Ws[4] = {(const float*)d_in[3], (const float*)d_in[5],
                          (const float*)d_in[7], (const float*)d_in[9]};
    const float* bs[4] = {(const float*)d_in[4], (const float*)d_in[6],
                          (const float*)d_in[8], (const float*)d_in[10]};
    float* out = (float*)d_out;

    void *xh, *xl, *wh, *wl, *xf, *wqf, *wkf, *qfp, *kfp, *vfp, *ch, *cl;
    cudaGetSymbolAddress(&xh, g_xh); cudaGetSymbolAddress(&xl, g_xl);
    cudaGetSymbolAddress(&wh, g_wh); cudaGetSymbolAddress(&wl, g_wl);
    cudaGetSymbolAddress(&xf, g_xf); cudaGetSymbolAddress(&wqf, g_wqf);
    cudaGetSymbolAddress(&wkf, g_wkf);
    cudaGetSymbolAddress(&qfp, g_qf); cudaGetSymbolAddress(&kfp, g_kf);
    cudaGetSymbolAddress(&vfp, g_vf);
    cudaGetSymbolAddress(&ch, g_ch); cudaGetSymbolAddress(&cl, g_cl);

    cudaFuncSetAttribute(gemm_f16, cudaFuncAttributeMaxDynamicSharedMemorySize, 2 * F_STG);
    cudaFuncSetAttribute(gemm_mma<3>, cudaFuncAttributeMaxDynamicSharedMemorySize, 2 * G_STG);
    cudaFuncSetAttribute(gemm_mma<0>, cudaFuncAttributeMaxDynamicSharedMemorySize, 2 * G_STG);
    cudaFuncSetAttribute(attn_mma, cudaFuncAttributeMaxDynamicSharedMemorySize, 2 * A_STG);

    mask_detect_kernel<<<1, 32>>>((const unsigned int*)pmask);
    {
        const size_t total = (size_t)NB * NH * NP_ * (FB_COLS / 8);
        fuse_kernel<<<(unsigned)((total + 255) / 256), 256>>>(abias, pmask);
    }

    split16_kernel<<<(XE / 4 + 255) / 256, 256>>>((const float4*)x, (uint32_t*)xf, XE / 4);
    split16_kernel<<<WE / 4 / 256, 256>>>((const float4*)Ws[0], (uint32_t*)wqf, WE / 4);
    split16_kernel<<<WE / 4 / 256, 256>>>((const float4*)Ws[1], (uint32_t*)wkf, WE / 4);
    split_kernel<<<(XE / 4 + 255) / 256, 256>>>((const float4*)x,
        (uint32_t*)xh, (uint32_t*)xl, XE / 4);
    split_kernel<<<WE / 4 / 256, 256>>>((const float4*)Ws[2],
        (uint32_t*)((__nv_bfloat16*)wh + (size_t)2 * WE),
        (uint32_t*)((__nv_bfloat16*)wl + (size_t)2 * WE), WE / 4);
    split_kernel<<<WE / 4 / 256, 256>>>((const float4*)Ws[3],
        (uint32_t*)((__nv_bfloat16*)wh + (size_t)3 * WE),
        (uint32_t*)((__nv_bfloat16*)wl + (size_t)3 * WE), WE / 4);

    dim3 gg(129, 8);
    gemm_f16<<<gg, 128, 2 * F_STG>>>((const __half*)xf, (const __half*)wqf, bs[0], (__half*)qfp);
    gemm_f16<<<gg, 128, 2 * F_STG>>>((const __half*)xf, (const __half*)wkf, bs[1], (__half*)kfp);
    gemm_mma<3><<<gg, 128, 2 * G_STG>>>((const __nv_bfloat16*)xh, (const __nv_bfloat16*)xl,
        (const __nv_bfloat16*)wh + (size_t)2 * WE, (const __nv_bfloat16*)wl + (size_t)2 * WE, bs[2],
        (__half*)vfp, nullptr);

    attn_mma<<<dim3(9, 64), 256, 2 * A_STG>>>();

    gemm_mma<0><<<gg, 128, 2 * G_STG>>>((const __nv_bfloat16*)ch, (const __nv_bfloat16*)cl,
        (const __nv_bfloat16*)wh + (size_t)3 * WE, (const __nv_bfloat16*)wl + (size_t)3 * WE, bs[3],
        nullptr, out);
}